// round 9
// baseline (speedup 1.0000x reference)
#include <cuda_runtime.h>
#include <cuda_bf16.h>
#include <math.h>
#include <stdint.h>

// Problem constants
#define BB  8
#define LQ  512
#define LK  1024
#define QD  768
#define HID 1024
#define MID 4096
#define NH  16
#define DH  64

// ---------------- scratch (device globals) ------------------------------------
__device__ float g_qp    [(size_t)BB*LQ*QD];
__device__ float g_q0p   [(size_t)BB*LQ*HID];
__device__ float g_v1    [(size_t)BB*LK*HID];
__device__ float g_v0    [(size_t)BB*LK*HID];
__device__ float g_scores[(size_t)BB*NH*LQ*LK];   // 268 MB fp32 (pre-softmax)
__device__ float g_atted [(size_t)BB*LQ*HID];
__device__ float g_tmp   [(size_t)BB*LQ*HID];
__device__ float g_attln [(size_t)BB*LQ*HID];
__device__ float g_ff    [(size_t)BB*LQ*HID];
__device__ float g_xraw  [(size_t)BB*HID];

// bf16 [hi|lo] split operands (GEMM iterates segments A:[hi,lo,hi] x B:[hi,hi,lo])
__device__ __nv_bfloat16 g_qpbf   [(size_t)BB*LQ*2*QD];
__device__ __nv_bfloat16 g_qbf    [(size_t)BB*LQ*2*QD];
__device__ __nv_bfloat16 g_kpbf   [(size_t)BB*LK*2*QD];
__device__ __nv_bfloat16 g_attlnbf[(size_t)BB*LQ*2*HID];
__device__ __nv_bfloat16 g_h1bf   [(size_t)BB*LQ*2*MID];
__device__ __nv_bfloat16 g_qhs    [(size_t)BB*NH*LQ*2*DH];   // per-head split, x0.125
__device__ __nv_bfloat16 g_khs    [(size_t)BB*NH*LK*2*DH];
__device__ __nv_bfloat16 g_vt     [(size_t)BB*NH*128*2*LK];  // [z][n:v1|v0][hi|lo]
__device__ __nv_bfloat16 g_atts   [(size_t)BB*NH*LQ*2*LK];   // split softmax probs
__device__ __nv_bfloat16 g_Wqbf  [(size_t)HID*2*QD];
__device__ __nv_bfloat16 g_Wq0bf [(size_t)HID*2*QD];
__device__ __nv_bfloat16 g_Wkbf  [(size_t)HID*2*QD];
__device__ __nv_bfloat16 g_Wvbf  [(size_t)HID*2*QD];
__device__ __nv_bfloat16 g_Wv0bf [(size_t)HID*2*QD];
__device__ __nv_bfloat16 g_W1bf  [(size_t)MID*2*HID];
__device__ __nv_bfloat16 g_W2bf  [(size_t)HID*2*MID];

// =================== helpers ==================================================
__device__ __forceinline__ uint32_t smem_u32(const void* p) {
    uint32_t a;
    asm("{ .reg .u64 t; cvta.to.shared.u64 t, %1; cvt.u32.u64 %0, t; }"
        : "=r"(a) : "l"(p));
    return a;
}
#define SWZ128(x) ((x) ^ (((x) >> 3) & 0x70))

__device__ __forceinline__ void cp_async16(uint32_t dst, const void* src) {
    asm volatile("cp.async.cg.shared.global [%0], [%1], 16;"
                 :: "r"(dst), "l"(src) : "memory");
}
#define CP_COMMIT() asm volatile("cp.async.commit_group;" ::: "memory")
#define CP_WAIT(n)  asm volatile("cp.async.wait_group %0;" :: "n"(n) : "memory")

__device__ __forceinline__ void ldsm_x4(uint32_t& r0, uint32_t& r1,
                                        uint32_t& r2, uint32_t& r3, uint32_t a) {
    asm volatile("ldmatrix.sync.aligned.m8n8.x4.shared.b16 {%0,%1,%2,%3}, [%4];"
                 : "=r"(r0), "=r"(r1), "=r"(r2), "=r"(r3) : "r"(a));
}
__device__ __forceinline__ void mma16816(float* c, const uint32_t* a,
                                         uint32_t b0, uint32_t b1) {
    asm volatile("mma.sync.aligned.m16n8k16.row.col.f32.bf16.bf16.f32 "
                 "{%0,%1,%2,%3}, {%4,%5,%6,%7}, {%8,%9}, {%0,%1,%2,%3};"
                 : "+f"(c[0]), "+f"(c[1]), "+f"(c[2]), "+f"(c[3])
                 : "r"(a[0]), "r"(a[1]), "r"(a[2]), "r"(a[3]), "r"(b0), "r"(b1));
}
__device__ __forceinline__ void split2(float v, __nv_bfloat16& hi, __nv_bfloat16& lo) {
    hi = __float2bfloat16(v);
    lo = __float2bfloat16(v - __bfloat162float(hi));
}

// ---------------- split conversions: [hi | lo] --------------------------------
__global__ void convA_split(const float* __restrict__ in, __nv_bfloat16* __restrict__ out,
                            int K, size_t total)
{
    size_t idx = (size_t)blockIdx.x * blockDim.x + threadIdx.x;
    if (idx >= total) return;
    size_t m = idx / K;
    int    k = (int)(idx % K);
    __nv_bfloat16 hi, lo; split2(in[idx], hi, lo);
    __nv_bfloat16* row = out + m * (size_t)(2 * K);
    row[k] = hi; row[K + k] = lo;
}

// W [K,N] fp32 -> [N, 2K] bf16 transposed split
__global__ void convB_split(const float* __restrict__ W, __nv_bfloat16* __restrict__ out,
                            int K, int N)
{
    __shared__ float t[32][33];
    int k0 = blockIdx.x * 32, n0 = blockIdx.y * 32;
    int x = threadIdx.x, y = threadIdx.y;   // 32 x 8
#pragma unroll
    for (int i = 0; i < 32; i += 8)
        t[y + i][x] = W[(size_t)(k0 + y + i) * N + n0 + x];
    __syncthreads();
#pragma unroll
    for (int i = 0; i < 32; i += 8) {
        int n = n0 + y + i, k = k0 + x;
        __nv_bfloat16 hi, lo; split2(t[x][y + i], hi, lo);
        __nv_bfloat16* row = out + (size_t)n * (2 * K);
        row[k] = hi; row[K + k] = lo;
    }
}

// v1,v0 [B*LK, HID] fp32 -> Vt [z=(b,h)][n(0..127: v1 dims | v0 dims)][hi|lo] (2*LK)
__global__ void vt_transpose(const float* __restrict__ v1, const float* __restrict__ v0,
                             __nv_bfloat16* __restrict__ vt)
{
    __shared__ float t[32][33];
    int z = blockIdx.z, b = z >> 4, h = z & 15;
    int kk0 = blockIdx.x * 32, nd0 = blockIdx.y * 32;
    int x = threadIdx.x, y = threadIdx.y;   // 32 x 8
    const float* src = (nd0 < 64) ? v1 : v0;
    int d0 = nd0 & 63;
#pragma unroll
    for (int i = 0; i < 32; i += 8)
        t[y + i][x] = src[(size_t)(b * LK + kk0 + y + i) * HID + h * DH + d0 + x];
    __syncthreads();
#pragma unroll
    for (int i = 0; i < 32; i += 8) {
        int n = nd0 + y + i, kk = kk0 + x;
        __nv_bfloat16 hi, lo; split2(t[x][y + i], hi, lo);
        __nv_bfloat16* row = vt + ((size_t)z * 128 + n) * (2 * LK);
        row[kk] = hi; row[LK + kk] = lo;
    }
}

// ---------------- bf16 mma.sync GEMM ------------------------------------------
// C[M,N] (256x128 CTA tile, 8 warps = 4m x 2n of 64x64) = 3 segment-products of
// A'[.,2K] x B'[.,2K]^T ; segments A [hi, lo, hi] x B [hi, hi, lo].
// 3-stage cp.async pipeline.
// modes: 0 = fp32 C (+z*offC); 1 = split [hi|lo] to Osp (rows 2*Kseg), bias/relu;
//        2 = per-head split to Osp ((b,h) batches, Lrow rows, scale folded);
//        3 = att@V scatter: C=atted, C2=tmp, z=(b,h).
#define STAGE_BYTES 49152               // A 32KB + B 16KB
#define GEMM_SMEM_BYTES (3 * STAGE_BYTES)

__global__ void __launch_bounds__(256, 1)
gemm_mma(const __nv_bfloat16* __restrict__ A, const __nv_bfloat16* __restrict__ B,
         const float* __restrict__ bias, float* __restrict__ C, float* __restrict__ C2,
         __nv_bfloat16* __restrict__ Osp,
         int K, int ldc,
         long long offA, long long offB, long long offC,
         int mode, int relu, float scale, int Kseg, int Lrow)
{
    extern __shared__ uint8_t dynsmem[];
    const uint32_t sb = smem_u32(dynsmem);
    const int tid = threadIdx.x;
    const int wid = tid >> 5, lane = tid & 31;
    const int m0 = blockIdx.y * 256, n0 = blockIdx.x * 128;
    const int wm = (wid & 3) * 64, wn = (wid >> 2) * 64;
    const int z = blockIdx.z;

    A += (size_t)z * offA;
    B += (size_t)z * offB;

    const int K2 = 2 * K;
    const int cps = K >> 6;          // chunks per segment
    const int nch = 3 * cps;
    const size_t abase = (size_t)m0 * K2;
    const size_t bbase = (size_t)n0 * K2;

    float acc[4][8][4] = {};

    auto load_stage = [&](int st, int ch) {
        int seg = (ch >= cps) ? ((ch >= 2 * cps) ? 2 : 1) : 0;
        int w64 = (ch - seg * cps) * 64;
        int koffA = ((seg == 1) ? K : 0) + w64;
        int koffB = ((seg == 2) ? K : 0) + w64;
        uint32_t base = (uint32_t)st * STAGE_BYTES;
#pragma unroll
        for (int i = 0; i < 8; i++) {                // A: 256 rows x 128B
            int idx = tid + i * 256;
            int r = idx >> 3, c = idx & 7;
            uint32_t so = SWZ128((uint32_t)(r * 128 + c * 16));
            cp_async16(sb + base + so, A + abase + (size_t)r * K2 + koffA + c * 8);
        }
#pragma unroll
        for (int i = 0; i < 4; i++) {                // B: 128 rows x 128B
            int idx = tid + i * 256;
            int r = idx >> 3, c = idx & 7;
            uint32_t so = SWZ128((uint32_t)(r * 128 + c * 16));
            cp_async16(sb + base + 32768u + so, B + bbase + (size_t)r * K2 + koffB + c * 8);
        }
        CP_COMMIT();
    };

    load_stage(0, 0);
    if (nch > 1) load_stage(1, 1);

    for (int ch = 0; ch < nch; ch++) {
        if (ch + 2 < nch) load_stage((ch + 2) % 3, ch + 2);
        if (ch + 2 < nch)      { CP_WAIT(2); }
        else if (ch + 1 < nch) { CP_WAIT(1); }
        else                   { CP_WAIT(0); }
        __syncthreads();

        uint32_t As = sb + (uint32_t)(ch % 3) * STAGE_BYTES;
        uint32_t Bs = As + 32768u;
#pragma unroll
        for (int ks = 0; ks < 4; ks++) {
            int kb = ks * 32 + ((lane >> 4) << 4);
            uint32_t a[4][4];
#pragma unroll
            for (int mi = 0; mi < 4; mi++) {
                int r = wm + mi * 16 + (lane & 15);
                ldsm_x4(a[mi][0], a[mi][1], a[mi][2], a[mi][3],
                        As + SWZ128((uint32_t)(r * 128 + kb)));
            }
            uint32_t b[4][4];
#pragma unroll
            for (int g = 0; g < 4; g++) {
                int r = wn + g * 16 + (lane & 15);
                ldsm_x4(b[g][0], b[g][1], b[g][2], b[g][3],
                        Bs + SWZ128((uint32_t)(r * 128 + kb)));
            }
#pragma unroll
            for (int mi = 0; mi < 4; mi++)
#pragma unroll
                for (int nj = 0; nj < 8; nj++) {
                    int g = nj >> 1;
                    uint32_t b0 = (nj & 1) ? b[g][1] : b[g][0];
                    uint32_t b1 = (nj & 1) ? b[g][3] : b[g][2];
                    mma16816(acc[mi][nj], a[mi], b0, b1);
                }
        }
        __syncthreads();
    }

    // ---- epilogue ----
    int rowg = lane >> 2, colg = (lane & 3) * 2;
#pragma unroll
    for (int mi = 0; mi < 4; mi++) {
#pragma unroll
        for (int nj = 0; nj < 8; nj++) {
            int c0 = n0 + wn + nj * 8 + colg;
            float bx = 0.f, by = 0.f;
            if (bias) { bx = bias[c0]; by = bias[c0 + 1]; }
#pragma unroll
            for (int half = 0; half < 2; half++) {
                int r = m0 + wm + mi * 16 + rowg + half * 8;
                float vx = (acc[mi][nj][half * 2 + 0] + bx) * scale;
                float vy = (acc[mi][nj][half * 2 + 1] + by) * scale;
                if (relu) { vx = fmaxf(vx, 0.f); vy = fmaxf(vy, 0.f); }
                if (mode == 0) {
                    float2 p = {vx, vy};
                    *(float2*)(C + (size_t)z * offC + (size_t)r * ldc + c0) = p;
                } else if (mode == 1) {
                    __nv_bfloat162 hp, lp;
                    split2(vx, hp.x, lp.x); split2(vy, hp.y, lp.y);
                    __nv_bfloat16* rw = Osp + (size_t)r * (2 * Kseg) + c0;
                    *(__nv_bfloat162*)(rw)        = hp;
                    *(__nv_bfloat162*)(rw + Kseg) = lp;
                } else if (mode == 2) {
                    int zz = (r / Lrow) * NH + (c0 >> 6);
                    int rr = r % Lrow, cc = c0 & 63;
                    __nv_bfloat162 hp, lp;
                    split2(vx, hp.x, lp.x); split2(vy, hp.y, lp.y);
                    __nv_bfloat16* rw = Osp + ((size_t)zz * Lrow + rr) * (2 * DH) + cc;
                    *(__nv_bfloat162*)(rw)      = hp;
                    *(__nv_bfloat162*)(rw + DH) = lp;
                } else { // mode 3
                    int b = z >> 4, h = z & 15;
                    float* dst = (c0 < 64) ? C : C2;
                    float2 p = {vx, vy};
                    *(float2*)(dst + ((size_t)(b * LQ + r)) * HID + h * DH + (c0 & 63)) = p;
                }
            }
        }
    }
}

// ---------------- positional encoding add ------------------------------------
__global__ void add_pe_kernel(const float* __restrict__ in, float* __restrict__ out,
                              int L, size_t total)
{
    size_t idx = (size_t)blockIdx.x * blockDim.x + threadIdx.x;
    if (idx >= total) return;
    int c = (int)(idx % QD);
    int l = (int)((idx / QD) % L);
    const float coef = -9.210340371976184f / 768.0f;   // -ln(10000)/dim
    float ang = (float)l * expf((float)(c & ~1) * coef);
    float pe  = (c & 1) ? cosf(ang) : sinf(ang);
    out[idx] = in[idx] + pe;
}

// ---------------- fused softmax + att_out -------------------------------------
__global__ void __launch_bounds__(512)
softmax_attout(const float* __restrict__ scores, __nv_bfloat16* __restrict__ atts,
               float* __restrict__ attout)
{
    extern __shared__ float sh[];   // 16 * 1024 floats
    int bx = blockIdx.x;
    int b = bx >> 9, q = bx & 511;
    int tid = threadIdx.x, w = tid >> 5, lane = tid & 31;

    const float* row = scores + ((size_t)(b * NH + w) * LQ + q) * LK;
    float4 v4[8];
    float mx = -INFINITY;
#pragma unroll
    for (int j = 0; j < 8; j++) {
        int i4 = lane + j * 32;
        v4[j] = *(const float4*)(row + i4 * 4);
        *(float4*)(sh + w * 1024 + i4 * 4) = v4[j];
        mx = fmaxf(mx, fmaxf(fmaxf(v4[j].x, v4[j].y), fmaxf(v4[j].z, v4[j].w)));
    }
#pragma unroll
    for (int o = 16; o > 0; o >>= 1) mx = fmaxf(mx, __shfl_xor_sync(0xFFFFFFFFu, mx, o));
    float sum = 0.f;
#pragma unroll
    for (int j = 0; j < 8; j++) {
        v4[j].x = expf(v4[j].x - mx); v4[j].y = expf(v4[j].y - mx);
        v4[j].z = expf(v4[j].z - mx); v4[j].w = expf(v4[j].w - mx);
        sum += (v4[j].x + v4[j].y) + (v4[j].z + v4[j].w);
    }
#pragma unroll
    for (int o = 16; o > 0; o >>= 1) sum += __shfl_xor_sync(0xFFFFFFFFu, sum, o);
    float inv = 1.f / sum;

    __nv_bfloat16* arow = atts + ((size_t)(b * NH + w) * LQ + q) * (2 * LK);
#pragma unroll
    for (int j = 0; j < 8; j++) {
        int c = (lane + j * 32) * 4;
        float p0 = v4[j].x * inv, p1 = v4[j].y * inv;
        float p2 = v4[j].z * inv, p3 = v4[j].w * inv;
        __nv_bfloat162 h01, l01, h23, l23;
        split2(p0, h01.x, l01.x); split2(p1, h01.y, l01.y);
        split2(p2, h23.x, l23.x); split2(p3, h23.y, l23.y);
        *(__nv_bfloat162*)(arow + c)            = h01;
        *(__nv_bfloat162*)(arow + c + 2)        = h23;
        *(__nv_bfloat162*)(arow + LK + c)       = l01;
        *(__nv_bfloat162*)(arow + LK + c + 2)   = l23;
    }
    __syncthreads();

    float s1 = 0.f, s2 = 0.f;
#pragma unroll
    for (int h = 0; h < NH; h++) {
        s1 += fmaxf(sh[h * 1024 + tid], 0.f);
        s2 += fmaxf(sh[h * 1024 + tid + 512], 0.f);
    }
    float* orow = attout + ((size_t)b * LQ + q) * LK;
    orow[tid]       = s1 * (1.f / NH);
    orow[tid + 512] = s2 * (1.f / NH);
}

// ---------------- bilinear reduce --------------------------------------------
__global__ void bilinear_kernel(const float* __restrict__ q0p,
                                const float* __restrict__ tmp,
                                float* __restrict__ xraw)
{
    int c = blockIdx.x * blockDim.x + threadIdx.x;
    int b = blockIdx.y;
    const float* a = q0p + (size_t)b * LQ * HID + c;
    const float* t = tmp + (size_t)b * LQ * HID + c;
    float s = 0.f;
    for (int v = 0; v < LQ; v++)
        s += a[(size_t)v * HID] * t[(size_t)v * HID];
    xraw[b * HID + c] = s;
}

// ---------------- custom LayerNorm (optional fused split-bf16 output) ---------
__global__ void __launch_bounds__(256)
ln_kernel(const float* __restrict__ in1, const float* __restrict__ in2,
          const float* __restrict__ ga, const float* __restrict__ gb,
          float* __restrict__ out, __nv_bfloat16* __restrict__ osp)
{
    size_t row = blockIdx.x;
    int t = threadIdx.x;
    const float* p1 = in1 + row * (size_t)HID;
    const float* p2 = in2 ? in2 + row * (size_t)HID : nullptr;
    float v[4];
    float s = 0.f;
#pragma unroll
    for (int i = 0; i < 4; i++) {
        int c = t + i * 256;
        v[i] = p1[c] + (p2 ? p2[c] : 0.f);
        s += v[i];
    }
    __shared__ float red[256];
    red[t] = s; __syncthreads();
    for (int o = 128; o > 0; o >>= 1) { if (t < o) red[t] += red[t + o]; __syncthreads(); }
    float mean = red[0] * (1.f / (float)HID);
    __syncthreads();
    float s2 = 0.f;
#pragma unroll
    for (int i = 0; i < 4; i++) { float d = v[i] - mean; s2 += d * d; }
    red[t] = s2; __syncthreads();
    for (int o = 128; o > 0; o >>= 1) { if (t < o) red[t] += red[t + o]; __syncthreads(); }
    float var = red[0] * (1.f / (float)(HID - 1));
    float inv = 1.f / (sqrtf(var) + 1e-6f);
#pragma unroll
    for (int i = 0; i < 4; i++) {
        int c = t + i * 256;
        float r = ga[c] * (v[i] - mean) * inv + gb[c];
        out[row * (size_t)HID + c] = r;
        if (osp) {
            __nv_bfloat16 hi, lo; split2(r, hi, lo);
            __nv_bfloat16* rw = osp + row * (size_t)(2 * HID);
            rw[c] = hi; rw[HID + c] = lo;
        }
    }
}

// =============================================================================
extern "C" void kernel_launch(void* const* d_in, const int* in_sizes, int n_in,
                              void* d_out, int out_size)
{
    const float* q    = (const float*)d_in[0];
    const float* k    = (const float*)d_in[1];
    const float* Wq   = (const float*)d_in[2];
    const float* bq   = (const float*)d_in[3];
    const float* Wk   = (const float*)d_in[4];
    const float* bk   = (const float*)d_in[5];
    const float* Wv   = (const float*)d_in[6];
    const float* bv   = (const float*)d_in[7];
    const float* Wv0  = (const float*)d_in[8];
    const float* bv0  = (const float*)d_in[9];
    const float* Wq0  = (const float*)d_in[10];
    const float* bq0  = (const float*)d_in[11];
    const float* nq_a = (const float*)d_in[12];
    const float* nq_b = (const float*)d_in[13];
    const float* nx_a = (const float*)d_in[14];
    const float* nx_b = (const float*)d_in[15];
    const float* W1   = (const float*)d_in[16];
    const float* b1   = (const float*)d_in[17];
    const float* W2   = (const float*)d_in[18];
    const float* b2   = (const float*)d_in[19];
    const float* ns_a = (const float*)d_in[20];
    const float* ns_b = (const float*)d_in[21];

    float* out = (float*)d_out;
    const size_t OFF_X   = 0;
    const size_t OFF_QQ  = OFF_X  + (size_t)BB * HID;
    const size_t OFF_KP  = OFF_QQ + (size_t)BB * LQ * HID;
    const size_t OFF_ATT = OFF_KP + (size_t)BB * LK * QD;

    float *qp, *q0p, *v1, *v0, *scores, *atted, *tmp, *attln, *ff, *xraw;
    __nv_bfloat16 *qpbf, *qbf, *kpbf, *attlnbf, *h1bf, *qhs, *khs, *vt, *atts;
    __nv_bfloat16 *Wqbf, *Wq0bf, *Wkbf, *Wvbf, *Wv0bf, *W1bf, *W2bf;
    cudaGetSymbolAddress((void**)&qp,     g_qp);
    cudaGetSymbolAddress((void**)&q0p,    g_q0p);
    cudaGetSymbolAddress((void**)&v1,     g_v1);
    cudaGetSymbolAddress((void**)&v0,     g_v0);
    cudaGetSymbolAddress((void**)&scores, g_scores);
    cudaGetSymbolAddress((void**)&atted,  g_atted);
    cudaGetSymbolAddress((void**)&tmp,    g_tmp);
    cudaGetSymbolAddress((void**)&attln,  g_attln);
    cudaGetSymbolAddress((void**)&ff,     g_ff);
    cudaGetSymbolAddress((void**)&xraw,   g_xraw);
    cudaGetSymbolAddress((void**)&qpbf,   g_qpbf);
    cudaGetSymbolAddress((void**)&qbf,    g_qbf);
    cudaGetSymbolAddress((void**)&kpbf,   g_kpbf);
    cudaGetSymbolAddress((void**)&attlnbf,g_attlnbf);
    cudaGetSymbolAddress((void**)&h1bf,   g_h1bf);
    cudaGetSymbolAddress((void**)&qhs,    g_qhs);
    cudaGetSymbolAddress((void**)&khs,    g_khs);
    cudaGetSymbolAddress((void**)&vt,     g_vt);
    cudaGetSymbolAddress((void**)&atts,   g_atts);
    cudaGetSymbolAddress((void**)&Wqbf,   g_Wqbf);
    cudaGetSymbolAddress((void**)&Wq0bf,  g_Wq0bf);
    cudaGetSymbolAddress((void**)&Wkbf,   g_Wkbf);
    cudaGetSymbolAddress((void**)&Wvbf,   g_Wvbf);
    cudaGetSymbolAddress((void**)&Wv0bf,  g_Wv0bf);
    cudaGetSymbolAddress((void**)&W1bf,   g_W1bf);
    cudaGetSymbolAddress((void**)&W2bf,   g_W2bf);

    cudaFuncSetAttribute(gemm_mma, cudaFuncAttributeMaxDynamicSharedMemorySize,
                         GEMM_SMEM_BYTES);
    cudaFuncSetAttribute(softmax_attout, cudaFuncAttributeMaxDynamicSharedMemorySize,
                         16 * 1024 * (int)sizeof(float));

    float* kp = out + OFF_KP;
    const int MQ = BB * LQ;     // 4096
    const int MK = BB * LK;     // 8192

    // 1) positional encodings
    {
        size_t tq = (size_t)BB * LQ * QD;
        add_pe_kernel<<<(unsigned)((tq + 255) / 256), 256>>>(q, qp, LQ, tq);
        size_t tk = (size_t)BB * LK * QD;
        add_pe_kernel<<<(unsigned)((tk + 255) / 256), 256>>>(k, kp, LK, tk);
    }

    // 2) split conversions
    {
        size_t t1 = (size_t)MQ * QD;
        convA_split<<<(unsigned)((t1 + 255) / 256), 256>>>(qp, qpbf, QD, t1);
        convA_split<<<(unsigned)((t1 + 255) / 256), 256>>>(q,  qbf,  QD, t1);
        size_t t2 = (size_t)MK * QD;
        convA_split<<<(unsigned)((t2 + 255) / 256), 256>>>(kp, kpbf, QD, t2);
        dim3 bb(32, 8);
        convB_split<<<dim3(QD / 32, HID / 32), bb>>>(Wq,  Wqbf,  QD, HID);
        convB_split<<<dim3(QD / 32, HID / 32), bb>>>(Wq0, Wq0bf, QD, HID);
        convB_split<<<dim3(QD / 32, HID / 32), bb>>>(Wk,  Wkbf,  QD, HID);
        convB_split<<<dim3(QD / 32, HID / 32), bb>>>(Wv,  Wvbf,  QD, HID);
        convB_split<<<dim3(QD / 32, HID / 32), bb>>>(Wv0, Wv0bf, QD, HID);
        convB_split<<<dim3(HID / 32, MID / 32), bb>>>(W1, W1bf, HID, MID);
        convB_split<<<dim3(MID / 32, HID / 32), bb>>>(W2, W2bf, MID, HID);
    }

    // 3) projections
    gemm_mma<<<dim3(HID / 128, MQ / 256, 1), 256, GEMM_SMEM_BYTES>>>(
        qpbf, Wqbf, bq, nullptr, nullptr, qhs,
        QD, 0, 0, 0, 0, 2, 0, 0.125f, 0, LQ);
    gemm_mma<<<dim3(HID / 128, MK / 256, 1), 256, GEMM_SMEM_BYTES>>>(
        kpbf, Wkbf, bk, nullptr, nullptr, khs,
        QD, 0, 0, 0, 0, 2, 0, 1.f, 0, LK);
    gemm_mma<<<dim3(HID / 128, MQ / 256, 1), 256, GEMM_SMEM_BYTES>>>(
        qbf, Wq0bf, bq0, q0p, nullptr, nullptr,
        QD, HID, 0, 0, 0, 0, 0, 1.f, 0, 0);
    gemm_mma<<<dim3(HID / 128, MK / 256, 1), 256, GEMM_SMEM_BYTES>>>(
        kpbf, Wvbf, bv, v1, nullptr, nullptr,
        QD, HID, 0, 0, 0, 0, 0, 1.f, 0, 0);
    gemm_mma<<<dim3(HID / 128, MK / 256, 1), 256, GEMM_SMEM_BYTES>>>(
        kpbf, Wv0bf, bv0, v0, nullptr, nullptr,
        QD, HID, 0, 0, 0, 0, 0, 1.f, 0, 0);

    // 4) Vt transpose-split
    vt_transpose<<<dim3(LK / 32, 128 / 32, BB * NH), dim3(32, 8)>>>(v1, v0, vt);

    // 5) scores = qhs @ khs^T (batched HMMA, K=64, pre-scaled)
    gemm_mma<<<dim3(LK / 128, LQ / 256, BB * NH), 256, GEMM_SMEM_BYTES>>>(
        qhs, khs, nullptr, scores, nullptr, nullptr,
        DH, LK,
        (long long)LQ * 2 * DH, (long long)LK * 2 * DH, (long long)LQ * LK,
        0, 0, 1.f, 0, 0);

    // 6) fused softmax (split bf16 out) + att_out
    softmax_attout<<<BB * LQ, 512, 16 * 1024 * sizeof(float)>>>(
        scores, atts, out + OFF_ATT);

    // 7) [atted | tmp] = att @ [v1 | v0] (batched HMMA, N=128, K=1024)
    gemm_mma<<<dim3(1, LQ / 256, BB * NH), 256, GEMM_SMEM_BYTES>>>(
        atts, vt, nullptr, atted, tmp, nullptr,
        LK, 0,
        (long long)LQ * 2 * LK, (long long)128 * 2 * LK, 0,
        3, 0, 1.f, 0, 0);

    // 8) bilinear + LN -> x
    bilinear_kernel<<<dim3(HID / 256, BB), 256>>>(q0p, tmp, xraw);
    ln_kernel<<<BB, 256>>>(xraw, nullptr, nx_a, nx_b, out + OFF_X, nullptr);

    // 9) atted = LN(q0p + atted_raw), fused split-bf16 output
    ln_kernel<<<MQ, 256>>>(q0p, atted, nq_a, nq_b, attln, attlnbf);

    // 10) FFN
    gemm_mma<<<dim3(MID / 128, MQ / 256, 1), 256, GEMM_SMEM_BYTES>>>(
        attlnbf, W1bf, b1, nullptr, nullptr, h1bf,
        HID, 0, 0, 0, 0, 1, 1, 1.f, MID, 0);
    gemm_mma<<<dim3(HID / 128, MQ / 256, 1), 256, GEMM_SMEM_BYTES>>>(
        h1bf, W2bf, b2, ff, nullptr, nullptr,
        MID, HID, 0, 0, 0, 0, 0, 1.f, 0, 0);
    ln_kernel<<<MQ, 256>>>(attln, ff, ns_a, ns_b, out + OFF_QQ, nullptr);
}

// round 10
// speedup vs baseline: 1.7118x; 1.7118x over previous
#include <cuda_runtime.h>
#include <cuda_bf16.h>
#include <math.h>
#include <stdint.h>

// Problem constants
#define BB  8
#define LQ  512
#define LK  1024
#define QD  768
#define HID 1024
#define MID 4096
#define NH  16
#define DH  64

// ---------------- scratch (device globals) ------------------------------------
__device__ float g_qp    [(size_t)BB*LQ*QD];
__device__ float g_q0p   [(size_t)BB*LQ*HID];
__device__ float g_v1    [(size_t)BB*LK*HID];
__device__ float g_v0    [(size_t)BB*LK*HID];
__device__ float g_scores[(size_t)BB*NH*LQ*LK];   // 268 MB fp32 (pre-softmax)
__device__ float g_atted [(size_t)BB*LQ*HID];
__device__ float g_tmp   [(size_t)BB*LQ*HID];
__device__ float g_attln [(size_t)BB*LQ*HID];
__device__ float g_ff    [(size_t)BB*LQ*HID];
__device__ float g_xraw  [(size_t)BB*HID];

// bf16 [hi|lo] split operands (GEMM iterates segments A:[hi,lo,hi] x B:[hi,hi,lo])
__device__ __nv_bfloat16 g_qpbf   [(size_t)BB*LQ*2*QD];
__device__ __nv_bfloat16 g_qbf    [(size_t)BB*LQ*2*QD];
__device__ __nv_bfloat16 g_kpbf   [(size_t)BB*LK*2*QD];
__device__ __nv_bfloat16 g_attlnbf[(size_t)BB*LQ*2*HID];
__device__ __nv_bfloat16 g_h1bf   [(size_t)BB*LQ*2*MID];
__device__ __nv_bfloat16 g_qhs    [(size_t)BB*NH*LQ*2*DH];   // per-head split, x0.125
__device__ __nv_bfloat16 g_khs    [(size_t)BB*NH*LK*2*DH];
__device__ __nv_bfloat16 g_vt     [(size_t)BB*NH*128*2*LK];  // [z][n:v1|v0][hi|lo]
__device__ __nv_bfloat16 g_atts   [(size_t)BB*NH*LQ*2*LK];   // split softmax probs
__device__ __nv_bfloat16 g_Wqbf  [(size_t)HID*2*QD];
__device__ __nv_bfloat16 g_Wq0bf [(size_t)HID*2*QD];
__device__ __nv_bfloat16 g_Wkbf  [(size_t)HID*2*QD];
__device__ __nv_bfloat16 g_Wvbf  [(size_t)HID*2*QD];
__device__ __nv_bfloat16 g_Wv0bf [(size_t)HID*2*QD];
__device__ __nv_bfloat16 g_W1bf  [(size_t)MID*2*HID];
__device__ __nv_bfloat16 g_W2bf  [(size_t)HID*2*MID];

// =================== helpers ==================================================
__device__ __forceinline__ uint32_t smem_u32(const void* p) {
    uint32_t a;
    asm("{ .reg .u64 t; cvta.to.shared.u64 t, %1; cvt.u32.u64 %0, t; }"
        : "=r"(a) : "l"(p));
    return a;
}
#define SWZ128(x) ((x) ^ (((x) >> 3) & 0x70))

__device__ __forceinline__ void cp_async16(uint32_t dst, const void* src) {
    asm volatile("cp.async.cg.shared.global [%0], [%1], 16;"
                 :: "r"(dst), "l"(src) : "memory");
}
#define CP_COMMIT() asm volatile("cp.async.commit_group;" ::: "memory")
#define CP_WAIT(n)  asm volatile("cp.async.wait_group %0;" :: "n"(n) : "memory")

__device__ __forceinline__ void ldsm_x4(uint32_t& r0, uint32_t& r1,
                                        uint32_t& r2, uint32_t& r3, uint32_t a) {
    asm volatile("ldmatrix.sync.aligned.m8n8.x4.shared.b16 {%0,%1,%2,%3}, [%4];"
                 : "=r"(r0), "=r"(r1), "=r"(r2), "=r"(r3) : "r"(a));
}
__device__ __forceinline__ void mma16816(float* c, const uint32_t* a,
                                         uint32_t b0, uint32_t b1) {
    asm volatile("mma.sync.aligned.m16n8k16.row.col.f32.bf16.bf16.f32 "
                 "{%0,%1,%2,%3}, {%4,%5,%6,%7}, {%8,%9}, {%0,%1,%2,%3};"
                 : "+f"(c[0]), "+f"(c[1]), "+f"(c[2]), "+f"(c[3])
                 : "r"(a[0]), "r"(a[1]), "r"(a[2]), "r"(a[3]), "r"(b0), "r"(b1));
}
__device__ __forceinline__ void split2(float v, __nv_bfloat16& hi, __nv_bfloat16& lo) {
    hi = __float2bfloat16(v);
    lo = __float2bfloat16(v - __bfloat162float(hi));
}

// ---------------- split conversions: [hi | lo] --------------------------------
__global__ void convA_split(const float* __restrict__ in, __nv_bfloat16* __restrict__ out,
                            int K, size_t total)
{
    size_t idx = (size_t)blockIdx.x * blockDim.x + threadIdx.x;
    if (idx >= total) return;
    size_t m = idx / K;
    int    k = (int)(idx % K);
    __nv_bfloat16 hi, lo; split2(in[idx], hi, lo);
    __nv_bfloat16* row = out + m * (size_t)(2 * K);
    row[k] = hi; row[K + k] = lo;
}

// W [K,N] fp32 -> [N, 2K] bf16 transposed split
__global__ void convB_split(const float* __restrict__ W, __nv_bfloat16* __restrict__ out,
                            int K, int N)
{
    __shared__ float t[32][33];
    int k0 = blockIdx.x * 32, n0 = blockIdx.y * 32;
    int x = threadIdx.x, y = threadIdx.y;   // 32 x 8
#pragma unroll
    for (int i = 0; i < 32; i += 8)
        t[y + i][x] = W[(size_t)(k0 + y + i) * N + n0 + x];
    __syncthreads();
#pragma unroll
    for (int i = 0; i < 32; i += 8) {
        int n = n0 + y + i, k = k0 + x;
        __nv_bfloat16 hi, lo; split2(t[x][y + i], hi, lo);
        __nv_bfloat16* row = out + (size_t)n * (2 * K);
        row[k] = hi; row[K + k] = lo;
    }
}

// v1,v0 [B*LK, HID] fp32 -> Vt [z=(b,h)][n(0..127: v1 dims | v0 dims)][hi|lo] (2*LK)
__global__ void vt_transpose(const float* __restrict__ v1, const float* __restrict__ v0,
                             __nv_bfloat16* __restrict__ vt)
{
    __shared__ float t[32][33];
    int z = blockIdx.z, b = z >> 4, h = z & 15;
    int kk0 = blockIdx.x * 32, nd0 = blockIdx.y * 32;
    int x = threadIdx.x, y = threadIdx.y;   // 32 x 8
    const float* src = (nd0 < 64) ? v1 : v0;
    int d0 = nd0 & 63;
#pragma unroll
    for (int i = 0; i < 32; i += 8)
        t[y + i][x] = src[(size_t)(b * LK + kk0 + y + i) * HID + h * DH + d0 + x];
    __syncthreads();
#pragma unroll
    for (int i = 0; i < 32; i += 8) {
        int n = nd0 + y + i, kk = kk0 + x;
        __nv_bfloat16 hi, lo; split2(t[x][y + i], hi, lo);
        __nv_bfloat16* row = vt + ((size_t)z * 128 + n) * (2 * LK);
        row[kk] = hi; row[LK + kk] = lo;
    }
}

// ---------------- bf16 mma.sync GEMM ------------------------------------------
// C[M,N] (128x128 CTA tile, 8 warps = 4m x 2n of 32x64) = 3 segment-products of
// A'[.,2K] x B'[.,2K]^T ; segments A [hi, lo, hi] x B [hi, hi, lo].
// 3-stage cp.async pipeline, 2 CTAs/SM.
// modes: 0 = fp32 C (+z*offC); 1 = split [hi|lo] to Osp (rows 2*Kseg), bias/relu;
//        2 = per-head split to Osp ((b,h) batches, Lrow rows, scale folded);
//        3 = att@V scatter: C=atted, C2=tmp, z=(b,h).
#define STAGE_BYTES 32768               // A 16KB + B 16KB
#define GEMM_SMEM_BYTES (3 * STAGE_BYTES)

__global__ void __launch_bounds__(256, 2)
gemm_mma(const __nv_bfloat16* __restrict__ A, const __nv_bfloat16* __restrict__ B,
         const float* __restrict__ bias, float* __restrict__ C, float* __restrict__ C2,
         __nv_bfloat16* __restrict__ Osp,
         int K, int ldc,
         long long offA, long long offB, long long offC,
         int mode, int relu, float scale, int Kseg, int Lrow)
{
    extern __shared__ uint8_t dynsmem[];
    const uint32_t sb = smem_u32(dynsmem);
    const int tid = threadIdx.x;
    const int wid = tid >> 5, lane = tid & 31;
    const int m0 = blockIdx.y * 128, n0 = blockIdx.x * 128;
    const int wm = (wid & 3) * 32, wn = (wid >> 2) * 64;
    const int z = blockIdx.z;

    A += (size_t)z * offA;
    B += (size_t)z * offB;

    const int K2 = 2 * K;
    const int cps = K >> 6;          // chunks per segment
    const int nch = 3 * cps;
    const size_t abase = (size_t)m0 * K2;
    const size_t bbase = (size_t)n0 * K2;

    float acc[2][8][4] = {};

    auto load_stage = [&](int st, int ch) {
        int seg = (ch >= cps) ? ((ch >= 2 * cps) ? 2 : 1) : 0;
        int w64 = (ch - seg * cps) * 64;
        int koffA = ((seg == 1) ? K : 0) + w64;
        int koffB = ((seg == 2) ? K : 0) + w64;
        uint32_t base = (uint32_t)st * STAGE_BYTES;
#pragma unroll
        for (int i = 0; i < 4; i++) {
            int idx = tid + i * 256;
            int r = idx >> 3, c = idx & 7;
            uint32_t so = SWZ128((uint32_t)(r * 128 + c * 16));
            cp_async16(sb + base + so, A + abase + (size_t)r * K2 + koffA + c * 8);
            cp_async16(sb + base + 16384u + so, B + bbase + (size_t)r * K2 + koffB + c * 8);
        }
        CP_COMMIT();
    };

    load_stage(0, 0);
    if (nch > 1) load_stage(1, 1);

    for (int ch = 0; ch < nch; ch++) {
        if (ch + 2 < nch) load_stage((ch + 2) % 3, ch + 2);
        if (ch + 2 < nch)      { CP_WAIT(2); }
        else if (ch + 1 < nch) { CP_WAIT(1); }
        else                   { CP_WAIT(0); }
        __syncthreads();

        uint32_t As = sb + (uint32_t)(ch % 3) * STAGE_BYTES;
        uint32_t Bs = As + 16384u;
#pragma unroll
        for (int ks = 0; ks < 4; ks++) {
            int kb = ks * 32 + ((lane >> 4) << 4);
            uint32_t a[2][4];
#pragma unroll
            for (int mi = 0; mi < 2; mi++) {
                int r = wm + mi * 16 + (lane & 15);
                ldsm_x4(a[mi][0], a[mi][1], a[mi][2], a[mi][3],
                        As + SWZ128((uint32_t)(r * 128 + kb)));
            }
            uint32_t b[4][4];
#pragma unroll
            for (int g = 0; g < 4; g++) {
                int r = wn + g * 16 + (lane & 15);
                ldsm_x4(b[g][0], b[g][1], b[g][2], b[g][3],
                        Bs + SWZ128((uint32_t)(r * 128 + kb)));
            }
#pragma unroll
            for (int mi = 0; mi < 2; mi++)
#pragma unroll
                for (int nj = 0; nj < 8; nj++) {
                    int g = nj >> 1;
                    uint32_t b0 = (nj & 1) ? b[g][1] : b[g][0];
                    uint32_t b1 = (nj & 1) ? b[g][3] : b[g][2];
                    mma16816(acc[mi][nj], a[mi], b0, b1);
                }
        }
        __syncthreads();
    }

    // ---- epilogue ----
    int rowg = lane >> 2, colg = (lane & 3) * 2;
#pragma unroll
    for (int mi = 0; mi < 2; mi++) {
#pragma unroll
        for (int nj = 0; nj < 8; nj++) {
            int c0 = n0 + wn + nj * 8 + colg;
            float bx = 0.f, by = 0.f;
            if (bias) { bx = bias[c0]; by = bias[c0 + 1]; }
#pragma unroll
            for (int half = 0; half < 2; half++) {
                int r = m0 + wm + mi * 16 + rowg + half * 8;
                float vx = (acc[mi][nj][half * 2 + 0] + bx) * scale;
                float vy = (acc[mi][nj][half * 2 + 1] + by) * scale;
                if (relu) { vx = fmaxf(vx, 0.f); vy = fmaxf(vy, 0.f); }
                if (mode == 0) {
                    float2 p = {vx, vy};
                    *(float2*)(C + (size_t)z * offC + (size_t)r * ldc + c0) = p;
                } else if (mode == 1) {
                    __nv_bfloat162 hp, lp;
                    split2(vx, hp.x, lp.x); split2(vy, hp.y, lp.y);
                    __nv_bfloat16* rw = Osp + (size_t)r * (2 * Kseg) + c0;
                    *(__nv_bfloat162*)(rw)        = hp;
                    *(__nv_bfloat162*)(rw + Kseg) = lp;
                } else if (mode == 2) {
                    int zz = (r / Lrow) * NH + (c0 >> 6);
                    int rr = r % Lrow, cc = c0 & 63;
                    __nv_bfloat162 hp, lp;
                    split2(vx, hp.x, lp.x); split2(vy, hp.y, lp.y);
                    __nv_bfloat16* rw = Osp + ((size_t)zz * Lrow + rr) * (2 * DH) + cc;
                    *(__nv_bfloat162*)(rw)      = hp;
                    *(__nv_bfloat162*)(rw + DH) = lp;
                } else { // mode 3
                    int b = z >> 4, h = z & 15;
                    float* dst = (c0 < 64) ? C : C2;
                    float2 p = {vx, vy};
                    *(float2*)(dst + ((size_t)(b * LQ + r)) * HID + h * DH + (c0 & 63)) = p;
                }
            }
        }
    }
}

// ---------------- positional encoding add ------------------------------------
__global__ void add_pe_kernel(const float* __restrict__ in, float* __restrict__ out,
                              int L, size_t total)
{
    size_t idx = (size_t)blockIdx.x * blockDim.x + threadIdx.x;
    if (idx >= total) return;
    int c = (int)(idx % QD);
    int l = (int)((idx / QD) % L);
    const float coef = -9.210340371976184f / 768.0f;   // -ln(10000)/dim
    float ang = (float)l * expf((float)(c & ~1) * coef);
    float pe  = (c & 1) ? cosf(ang) : sinf(ang);
    out[idx] = in[idx] + pe;
}

// ---------------- fused softmax + att_out -------------------------------------
__global__ void __launch_bounds__(512)
softmax_attout(const float* __restrict__ scores, __nv_bfloat16* __restrict__ atts,
               float* __restrict__ attout)
{
    extern __shared__ float sh[];   // 16 * 1024 floats
    int bx = blockIdx.x;
    int b = bx >> 9, q = bx & 511;
    int tid = threadIdx.x, w = tid >> 5, lane = tid & 31;

    const float* row = scores + ((size_t)(b * NH + w) * LQ + q) * LK;
    float4 v4[8];
    float mx = -INFINITY;
#pragma unroll
    for (int j = 0; j < 8; j++) {
        int i4 = lane + j * 32;
        v4[j] = *(const float4*)(row + i4 * 4);
        *(float4*)(sh + w * 1024 + i4 * 4) = v4[j];
        mx = fmaxf(mx, fmaxf(fmaxf(v4[j].x, v4[j].y), fmaxf(v4[j].z, v4[j].w)));
    }
#pragma unroll
    for (int o = 16; o > 0; o >>= 1) mx = fmaxf(mx, __shfl_xor_sync(0xFFFFFFFFu, mx, o));
    float sum = 0.f;
#pragma unroll
    for (int j = 0; j < 8; j++) {
        v4[j].x = expf(v4[j].x - mx); v4[j].y = expf(v4[j].y - mx);
        v4[j].z = expf(v4[j].z - mx); v4[j].w = expf(v4[j].w - mx);
        sum += (v4[j].x + v4[j].y) + (v4[j].z + v4[j].w);
    }
#pragma unroll
    for (int o = 16; o > 0; o >>= 1) sum += __shfl_xor_sync(0xFFFFFFFFu, sum, o);
    float inv = 1.f / sum;

    __nv_bfloat16* arow = atts + ((size_t)(b * NH + w) * LQ + q) * (2 * LK);
#pragma unroll
    for (int j = 0; j < 8; j++) {
        int c = (lane + j * 32) * 4;
        float p0 = v4[j].x * inv, p1 = v4[j].y * inv;
        float p2 = v4[j].z * inv, p3 = v4[j].w * inv;
        __nv_bfloat162 h01, l01, h23, l23;
        split2(p0, h01.x, l01.x); split2(p1, h01.y, l01.y);
        split2(p2, h23.x, l23.x); split2(p3, h23.y, l23.y);
        *(__nv_bfloat162*)(arow + c)            = h01;
        *(__nv_bfloat162*)(arow + c + 2)        = h23;
        *(__nv_bfloat162*)(arow + LK + c)       = l01;
        *(__nv_bfloat162*)(arow + LK + c + 2)   = l23;
    }
    __syncthreads();

    float s1 = 0.f, s2 = 0.f;
#pragma unroll
    for (int h = 0; h < NH; h++) {
        s1 += fmaxf(sh[h * 1024 + tid], 0.f);
        s2 += fmaxf(sh[h * 1024 + tid + 512], 0.f);
    }
    float* orow = attout + ((size_t)b * LQ + q) * LK;
    orow[tid]       = s1 * (1.f / NH);
    orow[tid + 512] = s2 * (1.f / NH);
}

// ---------------- bilinear reduce --------------------------------------------
__global__ void bilinear_kernel(const float* __restrict__ q0p,
                                const float* __restrict__ tmp,
                                float* __restrict__ xraw)
{
    int c = blockIdx.x * blockDim.x + threadIdx.x;
    int b = blockIdx.y;
    const float* a = q0p + (size_t)b * LQ * HID + c;
    const float* t = tmp + (size_t)b * LQ * HID + c;
    float s = 0.f;
    for (int v = 0; v < LQ; v++)
        s += a[(size_t)v * HID] * t[(size_t)v * HID];
    xraw[b * HID + c] = s;
}

// ---------------- custom LayerNorm (optional fused split-bf16 output) ---------
__global__ void __launch_bounds__(256)
ln_kernel(const float* __restrict__ in1, const float* __restrict__ in2,
          const float* __restrict__ ga, const float* __restrict__ gb,
          float* __restrict__ out, __nv_bfloat16* __restrict__ osp)
{
    size_t row = blockIdx.x;
    int t = threadIdx.x;
    const float* p1 = in1 + row * (size_t)HID;
    const float* p2 = in2 ? in2 + row * (size_t)HID : nullptr;
    float v[4];
    float s = 0.f;
#pragma unroll
    for (int i = 0; i < 4; i++) {
        int c = t + i * 256;
        v[i] = p1[c] + (p2 ? p2[c] : 0.f);
        s += v[i];
    }
    __shared__ float red[256];
    red[t] = s; __syncthreads();
    for (int o = 128; o > 0; o >>= 1) { if (t < o) red[t] += red[t + o]; __syncthreads(); }
    float mean = red[0] * (1.f / (float)HID);
    __syncthreads();
    float s2 = 0.f;
#pragma unroll
    for (int i = 0; i < 4; i++) { float d = v[i] - mean; s2 += d * d; }
    red[t] = s2; __syncthreads();
    for (int o = 128; o > 0; o >>= 1) { if (t < o) red[t] += red[t + o]; __syncthreads(); }
    float var = red[0] * (1.f / (float)(HID - 1));
    float inv = 1.f / (sqrtf(var) + 1e-6f);
#pragma unroll
    for (int i = 0; i < 4; i++) {
        int c = t + i * 256;
        float r = ga[c] * (v[i] - mean) * inv + gb[c];
        out[row * (size_t)HID + c] = r;
        if (osp) {
            __nv_bfloat16 hi, lo; split2(r, hi, lo);
            __nv_bfloat16* rw = osp + row * (size_t)(2 * HID);
            rw[c] = hi; rw[HID + c] = lo;
        }
    }
}

// =============================================================================
extern "C" void kernel_launch(void* const* d_in, const int* in_sizes, int n_in,
                              void* d_out, int out_size)
{
    const float* q    = (const float*)d_in[0];
    const float* k    = (const float*)d_in[1];
    const float* Wq   = (const float*)d_in[2];
    const float* bq   = (const float*)d_in[3];
    const float* Wk   = (const float*)d_in[4];
    const float* bk   = (const float*)d_in[5];
    const float* Wv   = (const float*)d_in[6];
    const float* bv   = (const float*)d_in[7];
    const float* Wv0  = (const float*)d_in[8];
    const float* bv0  = (const float*)d_in[9];
    const float* Wq0  = (const float*)d_in[10];
    const float* bq0  = (const float*)d_in[11];
    const float* nq_a = (const float*)d_in[12];
    const float* nq_b = (const float*)d_in[13];
    const float* nx_a = (const float*)d_in[14];
    const float* nx_b = (const float*)d_in[15];
    const float* W1   = (const float*)d_in[16];
    const float* b1   = (const float*)d_in[17];
    const float* W2   = (const float*)d_in[18];
    const float* b2   = (const float*)d_in[19];
    const float* ns_a = (const float*)d_in[20];
    const float* ns_b = (const float*)d_in[21];

    float* out = (float*)d_out;
    const size_t OFF_X   = 0;
    const size_t OFF_QQ  = OFF_X  + (size_t)BB * HID;
    const size_t OFF_KP  = OFF_QQ + (size_t)BB * LQ * HID;
    const size_t OFF_ATT = OFF_KP + (size_t)BB * LK * QD;

    float *qp, *q0p, *v1, *v0, *scores, *atted, *tmp, *attln, *ff, *xraw;
    __nv_bfloat16 *qpbf, *qbf, *kpbf, *attlnbf, *h1bf, *qhs, *khs, *vt, *atts;
    __nv_bfloat16 *Wqbf, *Wq0bf, *Wkbf, *Wvbf, *Wv0bf, *W1bf, *W2bf;
    cudaGetSymbolAddress((void**)&qp,     g_qp);
    cudaGetSymbolAddress((void**)&q0p,    g_q0p);
    cudaGetSymbolAddress((void**)&v1,     g_v1);
    cudaGetSymbolAddress((void**)&v0,     g_v0);
    cudaGetSymbolAddress((void**)&scores, g_scores);
    cudaGetSymbolAddress((void**)&atted,  g_atted);
    cudaGetSymbolAddress((void**)&tmp,    g_tmp);
    cudaGetSymbolAddress((void**)&attln,  g_attln);
    cudaGetSymbolAddress((void**)&ff,     g_ff);
    cudaGetSymbolAddress((void**)&xraw,   g_xraw);
    cudaGetSymbolAddress((void**)&qpbf,   g_qpbf);
    cudaGetSymbolAddress((void**)&qbf,    g_qbf);
    cudaGetSymbolAddress((void**)&kpbf,   g_kpbf);
    cudaGetSymbolAddress((void**)&attlnbf,g_attlnbf);
    cudaGetSymbolAddress((void**)&h1bf,   g_h1bf);
    cudaGetSymbolAddress((void**)&qhs,    g_qhs);
    cudaGetSymbolAddress((void**)&khs,    g_khs);
    cudaGetSymbolAddress((void**)&vt,     g_vt);
    cudaGetSymbolAddress((void**)&atts,   g_atts);
    cudaGetSymbolAddress((void**)&Wqbf,   g_Wqbf);
    cudaGetSymbolAddress((void**)&Wq0bf,  g_Wq0bf);
    cudaGetSymbolAddress((void**)&Wkbf,   g_Wkbf);
    cudaGetSymbolAddress((void**)&Wvbf,   g_Wvbf);
    cudaGetSymbolAddress((void**)&Wv0bf,  g_Wv0bf);
    cudaGetSymbolAddress((void**)&W1bf,   g_W1bf);
    cudaGetSymbolAddress((void**)&W2bf,   g_W2bf);

    cudaFuncSetAttribute(gemm_mma, cudaFuncAttributeMaxDynamicSharedMemorySize,
                         GEMM_SMEM_BYTES);
    cudaFuncSetAttribute(softmax_attout, cudaFuncAttributeMaxDynamicSharedMemorySize,
                         16 * 1024 * (int)sizeof(float));

    float* kp = out + OFF_KP;
    const int MQ = BB * LQ;     // 4096
    const int MK = BB * LK;     // 8192

    // 1) positional encodings
    {
        size_t tq = (size_t)BB * LQ * QD;
        add_pe_kernel<<<(unsigned)((tq + 255) / 256), 256>>>(q, qp, LQ, tq);
        size_t tk = (size_t)BB * LK * QD;
        add_pe_kernel<<<(unsigned)((tk + 255) / 256), 256>>>(k, kp, LK, tk);
    }

    // 2) split conversions
    {
        size_t t1 = (size_t)MQ * QD;
        convA_split<<<(unsigned)((t1 + 255) / 256), 256>>>(qp, qpbf, QD, t1);
        convA_split<<<(unsigned)((t1 + 255) / 256), 256>>>(q,  qbf,  QD, t1);
        size_t t2 = (size_t)MK * QD;
        convA_split<<<(unsigned)((t2 + 255) / 256), 256>>>(kp, kpbf, QD, t2);
        dim3 bb(32, 8);
        convB_split<<<dim3(QD / 32, HID / 32), bb>>>(Wq,  Wqbf,  QD, HID);
        convB_split<<<dim3(QD / 32, HID / 32), bb>>>(Wq0, Wq0bf, QD, HID);
        convB_split<<<dim3(QD / 32, HID / 32), bb>>>(Wk,  Wkbf,  QD, HID);
        convB_split<<<dim3(QD / 32, HID / 32), bb>>>(Wv,  Wvbf,  QD, HID);
        convB_split<<<dim3(QD / 32, HID / 32), bb>>>(Wv0, Wv0bf, QD, HID);
        convB_split<<<dim3(HID / 32, MID / 32), bb>>>(W1, W1bf, HID, MID);
        convB_split<<<dim3(MID / 32, HID / 32), bb>>>(W2, W2bf, MID, HID);
    }

    // 3) projections
    gemm_mma<<<dim3(HID / 128, MQ / 128, 1), 256, GEMM_SMEM_BYTES>>>(
        qpbf, Wqbf, bq, nullptr, nullptr, qhs,
        QD, 0, 0, 0, 0, 2, 0, 0.125f, 0, LQ);
    gemm_mma<<<dim3(HID / 128, MK / 128, 1), 256, GEMM_SMEM_BYTES>>>(
        kpbf, Wkbf, bk, nullptr, nullptr, khs,
        QD, 0, 0, 0, 0, 2, 0, 1.f, 0, LK);
    gemm_mma<<<dim3(HID / 128, MQ / 128, 1), 256, GEMM_SMEM_BYTES>>>(
        qbf, Wq0bf, bq0, q0p, nullptr, nullptr,
        QD, HID, 0, 0, 0, 0, 0, 1.f, 0, 0);
    gemm_mma<<<dim3(HID / 128, MK / 128, 1), 256, GEMM_SMEM_BYTES>>>(
        kpbf, Wvbf, bv, v1, nullptr, nullptr,
        QD, HID, 0, 0, 0, 0, 0, 1.f, 0, 0);
    gemm_mma<<<dim3(HID / 128, MK / 128, 1), 256, GEMM_SMEM_BYTES>>>(
        kpbf, Wv0bf, bv0, v0, nullptr, nullptr,
        QD, HID, 0, 0, 0, 0, 0, 1.f, 0, 0);

    // 4) Vt transpose-split
    vt_transpose<<<dim3(LK / 32, 128 / 32, BB * NH), dim3(32, 8)>>>(v1, v0, vt);

    // 5) scores = qhs @ khs^T (batched HMMA, K=64, pre-scaled)
    gemm_mma<<<dim3(LK / 128, LQ / 128, BB * NH), 256, GEMM_SMEM_BYTES>>>(
        qhs, khs, nullptr, scores, nullptr, nullptr,
        DH, LK,
        (long long)LQ * 2 * DH, (long long)LK * 2 * DH, (long long)LQ * LK,
        0, 0, 1.f, 0, 0);

    // 6) fused softmax (split bf16 out) + att_out
    softmax_attout<<<BB * LQ, 512, 16 * 1024 * sizeof(float)>>>(
        scores, atts, out + OFF_ATT);

    // 7) [atted | tmp] = att @ [v1 | v0] (batched HMMA, N=128, K=1024)
    gemm_mma<<<dim3(1, LQ / 128, BB * NH), 256, GEMM_SMEM_BYTES>>>(
        atts, vt, nullptr, atted, tmp, nullptr,
        LK, 0,
        (long long)LQ * 2 * LK, (long long)128 * 2 * LK, 0,
        3, 0, 1.f, 0, 0);

    // 8) bilinear + LN -> x
    bilinear_kernel<<<dim3(HID / 256, BB), 256>>>(q0p, tmp, xraw);
    ln_kernel<<<BB, 256>>>(xraw, nullptr, nx_a, nx_b, out + OFF_X, nullptr);

    // 9) atted = LN(q0p + atted_raw), fused split-bf16 output
    ln_kernel<<<MQ, 256>>>(q0p, atted, nq_a, nq_b, attln, attlnbf);

    // 10) FFN
    gemm_mma<<<dim3(MID / 128, MQ / 128, 1), 256, GEMM_SMEM_BYTES>>>(
        attlnbf, W1bf, b1, nullptr, nullptr, h1bf,
        HID, 0, 0, 0, 0, 1, 1, 1.f, MID, 0);
    gemm_mma<<<dim3(HID / 128, MQ / 128, 1), 256, GEMM_SMEM_BYTES>>>(
        h1bf, W2bf, b2, ff, nullptr, nullptr,
        MID, HID, 0, 0, 0, 0, 0, 1.f, 0, 0);
    ln_kernel<<<MQ, 256>>>(attln, ff, ns_a, ns_b, out + OFF_QQ, nullptr);
}

// round 11
// speedup vs baseline: 2.2927x; 1.3394x over previous
#include <cuda_runtime.h>
#include <cuda_fp16.h>
#include <math.h>
#include <stdint.h>

// Problem constants
#define BB  8
#define LQ  512
#define LK  1024
#define QD  768
#define HID 1024
#define MID 4096
#define NH  16
#define DH  64

// ---------------- scratch (device globals) ------------------------------------
__device__ float g_qp    [(size_t)BB*LQ*QD];
__device__ float g_q0p   [(size_t)BB*LQ*HID];
__device__ float g_v1    [(size_t)BB*LK*HID];
__device__ float g_v0    [(size_t)BB*LK*HID];
__device__ float g_scores[(size_t)BB*NH*LQ*LK];   // 268 MB fp32 (pre-softmax)
__device__ float g_atted [(size_t)BB*LQ*HID];
__device__ float g_tmp   [(size_t)BB*LQ*HID];
__device__ float g_attln [(size_t)BB*LQ*HID];
__device__ float g_ff    [(size_t)BB*LQ*HID];
__device__ float g_xraw  [(size_t)BB*HID];

// fp16 operands: A-side 2-term [hi|lo] (row stride 2K), B-side single fp16.
__device__ __half g_qpbf   [(size_t)BB*LQ*2*QD];
__device__ __half g_qbf    [(size_t)BB*LQ*2*QD];
__device__ __half g_kpbf   [(size_t)BB*LK*2*QD];
__device__ __half g_attlnbf[(size_t)BB*LQ*2*HID];
__device__ __half g_h1bf   [(size_t)BB*LQ*2*MID];
__device__ __half g_qhs    [(size_t)BB*NH*LQ*2*DH];   // per-head 2-term, x0.125
__device__ __half g_khs    [(size_t)BB*NH*LK*DH];     // per-head single
__device__ __half g_vt     [(size_t)BB*NH*128*LK];    // [z][n:v1|v0] single
__device__ __half g_atts   [(size_t)BB*NH*LQ*2*LK];   // 2-term softmax probs
__device__ __half g_Wqbf  [(size_t)HID*QD];
__device__ __half g_Wq0bf [(size_t)HID*QD];
__device__ __half g_Wkbf  [(size_t)HID*QD];
__device__ __half g_Wvbf  [(size_t)HID*QD];
__device__ __half g_Wv0bf [(size_t)HID*QD];
__device__ __half g_W1bf  [(size_t)MID*HID];
__device__ __half g_W2bf  [(size_t)HID*MID];

// =================== helpers ==================================================
__device__ __forceinline__ uint32_t smem_u32(const void* p) {
    uint32_t a;
    asm("{ .reg .u64 t; cvta.to.shared.u64 t, %1; cvt.u32.u64 %0, t; }"
        : "=r"(a) : "l"(p));
    return a;
}
#define SWZ128(x) ((x) ^ (((x) >> 3) & 0x70))

__device__ __forceinline__ void cp_async16(uint32_t dst, const void* src) {
    asm volatile("cp.async.cg.shared.global [%0], [%1], 16;"
                 :: "r"(dst), "l"(src) : "memory");
}
#define CP_COMMIT() asm volatile("cp.async.commit_group;" ::: "memory")
#define CP_WAIT(n)  asm volatile("cp.async.wait_group %0;" :: "n"(n) : "memory")

__device__ __forceinline__ void ldsm_x4(uint32_t& r0, uint32_t& r1,
                                        uint32_t& r2, uint32_t& r3, uint32_t a) {
    asm volatile("ldmatrix.sync.aligned.m8n8.x4.shared.b16 {%0,%1,%2,%3}, [%4];"
                 : "=r"(r0), "=r"(r1), "=r"(r2), "=r"(r3) : "r"(a));
}
__device__ __forceinline__ void mma16816(float* c, const uint32_t* a,
                                         uint32_t b0, uint32_t b1) {
    asm volatile("mma.sync.aligned.m16n8k16.row.col.f32.f16.f16.f32 "
                 "{%0,%1,%2,%3}, {%4,%5,%6,%7}, {%8,%9}, {%0,%1,%2,%3};"
                 : "+f"(c[0]), "+f"(c[1]), "+f"(c[2]), "+f"(c[3])
                 : "r"(a[0]), "r"(a[1]), "r"(a[2]), "r"(a[3]), "r"(b0), "r"(b1));
}
__device__ __forceinline__ void split2h(float v, __half& hi, __half& lo) {
    hi = __float2half(v);
    lo = __float2half(v - __half2float(hi));
}

// ---------------- conversions --------------------------------------------------
// A fp32 [M,K] -> fp16 2-term [M, 2K] ([hi | lo])
__global__ void convA_half(const float* __restrict__ in, __half* __restrict__ out,
                           int K, size_t total)
{
    size_t idx = (size_t)blockIdx.x * blockDim.x + threadIdx.x;
    if (idx >= total) return;
    size_t m = idx / K;
    int    k = (int)(idx % K);
    __half hi, lo; split2h(in[idx], hi, lo);
    __half* row = out + m * (size_t)(2 * K);
    row[k] = hi; row[K + k] = lo;
}

// W [K,N] fp32 -> [N,K] fp16 single (transposed)
__global__ void convB_half(const float* __restrict__ W, __half* __restrict__ out,
                           int K, int N)
{
    __shared__ float t[32][33];
    int k0 = blockIdx.x * 32, n0 = blockIdx.y * 32;
    int x = threadIdx.x, y = threadIdx.y;   // 32 x 8
#pragma unroll
    for (int i = 0; i < 32; i += 8)
        t[y + i][x] = W[(size_t)(k0 + y + i) * N + n0 + x];
    __syncthreads();
#pragma unroll
    for (int i = 0; i < 32; i += 8) {
        int n = n0 + y + i, k = k0 + x;
        out[(size_t)n * K + k] = __float2half(t[x][y + i]);
    }
}

// v1,v0 [B*LK, HID] fp32 -> Vt [z][n(0..127: v1|v0)][LK] fp16 single
__global__ void vt_transpose(const float* __restrict__ v1, const float* __restrict__ v0,
                             __half* __restrict__ vt)
{
    __shared__ float t[32][33];
    int z = blockIdx.z, b = z >> 4, h = z & 15;
    int kk0 = blockIdx.x * 32, nd0 = blockIdx.y * 32;
    int x = threadIdx.x, y = threadIdx.y;   // 32 x 8
    const float* src = (nd0 < 64) ? v1 : v0;
    int d0 = nd0 & 63;
#pragma unroll
    for (int i = 0; i < 32; i += 8)
        t[y + i][x] = src[(size_t)(b * LK + kk0 + y + i) * HID + h * DH + d0 + x];
    __syncthreads();
#pragma unroll
    for (int i = 0; i < 32; i += 8) {
        int n = nd0 + y + i, kk = kk0 + x;
        vt[((size_t)z * 128 + n) * LK + kk] = __float2half(t[x][y + i]);
    }
}

// ---------------- fp16 mma.sync GEMM --------------------------------------------
// C[M,N] (128x128 CTA tile, 8 warps of 32x64) = 2 segment-products:
//   seg0: Ahi x B ; seg1: Alo x B.   A row stride 2K, B row stride K.
// 3-stage cp.async pipeline, 2 CTAs/SM.
// modes: 0 = fp32 C (+z*offC); 1 = 2-term fp16 to Osp (rows 2*Kseg), bias/relu;
//        2 = per-head 2-term ((b,h) batches, Lrow rows); 3 = att@V fp32 scatter;
//        4 = per-head single fp16.
#define STAGE_BYTES 32768               // A 16KB + B 16KB
#define GEMM_SMEM_BYTES (3 * STAGE_BYTES)

__global__ void __launch_bounds__(256, 2)
gemm_mma(const __half* __restrict__ A, const __half* __restrict__ B,
         const float* __restrict__ bias, float* __restrict__ C, float* __restrict__ C2,
         __half* __restrict__ Osp,
         int K, int ldc,
         long long offA, long long offB, long long offC,
         int mode, int relu, float scale, int Kseg, int Lrow)
{
    extern __shared__ uint8_t dynsmem[];
    const uint32_t sb = smem_u32(dynsmem);
    const int tid = threadIdx.x;
    const int wid = tid >> 5, lane = tid & 31;
    const int m0 = blockIdx.y * 128, n0 = blockIdx.x * 128;
    const int wm = (wid & 3) * 32, wn = (wid >> 2) * 64;
    const int z = blockIdx.z;

    A += (size_t)z * offA;
    B += (size_t)z * offB;

    const int K2 = 2 * K;
    const int cps = K >> 6;          // 64-wide chunks per segment
    const int nch = 2 * cps;
    const size_t abase = (size_t)m0 * K2;
    const size_t bbase = (size_t)n0 * K;

    float acc[2][8][4] = {};

    auto load_stage = [&](int st, int ch) {
        int seg = (ch >= cps) ? 1 : 0;
        int w64 = (ch - seg * cps) * 64;
        int koffA = seg * K + w64;
        int koffB = w64;
        uint32_t base = (uint32_t)st * STAGE_BYTES;
#pragma unroll
        for (int i = 0; i < 4; i++) {
            int idx = tid + i * 256;
            int r = idx >> 3, c = idx & 7;
            uint32_t so = SWZ128((uint32_t)(r * 128 + c * 16));
            cp_async16(sb + base + so, A + abase + (size_t)r * K2 + koffA + c * 8);
            cp_async16(sb + base + 16384u + so, B + bbase + (size_t)r * K + koffB + c * 8);
        }
        CP_COMMIT();
    };

    load_stage(0, 0);
    if (nch > 1) load_stage(1, 1);

    for (int ch = 0; ch < nch; ch++) {
        if (ch + 2 < nch) load_stage((ch + 2) % 3, ch + 2);
        if (ch + 2 < nch)      { CP_WAIT(2); }
        else if (ch + 1 < nch) { CP_WAIT(1); }
        else                   { CP_WAIT(0); }
        __syncthreads();

        uint32_t As = sb + (uint32_t)(ch % 3) * STAGE_BYTES;
        uint32_t Bs = As + 16384u;
#pragma unroll
        for (int ks = 0; ks < 4; ks++) {
            int kb = ks * 32 + ((lane >> 4) << 4);
            uint32_t a[2][4];
#pragma unroll
            for (int mi = 0; mi < 2; mi++) {
                int r = wm + mi * 16 + (lane & 15);
                ldsm_x4(a[mi][0], a[mi][1], a[mi][2], a[mi][3],
                        As + SWZ128((uint32_t)(r * 128 + kb)));
            }
            uint32_t b[4][4];
#pragma unroll
            for (int g = 0; g < 4; g++) {
                int r = wn + g * 16 + (lane & 15);
                ldsm_x4(b[g][0], b[g][1], b[g][2], b[g][3],
                        Bs + SWZ128((uint32_t)(r * 128 + kb)));
            }
#pragma unroll
            for (int mi = 0; mi < 2; mi++)
#pragma unroll
                for (int nj = 0; nj < 8; nj++) {
                    int g = nj >> 1;
                    uint32_t b0 = (nj & 1) ? b[g][1] : b[g][0];
                    uint32_t b1 = (nj & 1) ? b[g][3] : b[g][2];
                    mma16816(acc[mi][nj], a[mi], b0, b1);
                }
        }
        __syncthreads();
    }

    // ---- epilogue ----
    int rowg = lane >> 2, colg = (lane & 3) * 2;
#pragma unroll
    for (int mi = 0; mi < 2; mi++) {
#pragma unroll
        for (int nj = 0; nj < 8; nj++) {
            int c0 = n0 + wn + nj * 8 + colg;
            float bx = 0.f, by = 0.f;
            if (bias) { bx = bias[c0]; by = bias[c0 + 1]; }
#pragma unroll
            for (int half = 0; half < 2; half++) {
                int r = m0 + wm + mi * 16 + rowg + half * 8;
                float vx = (acc[mi][nj][half * 2 + 0] + bx) * scale;
                float vy = (acc[mi][nj][half * 2 + 1] + by) * scale;
                if (relu) { vx = fmaxf(vx, 0.f); vy = fmaxf(vy, 0.f); }
                if (mode == 0) {
                    float2 p = {vx, vy};
                    *(float2*)(C + (size_t)z * offC + (size_t)r * ldc + c0) = p;
                } else if (mode == 1) {
                    __half2 hp, lp;
                    split2h(vx, hp.x, lp.x); split2h(vy, hp.y, lp.y);
                    __half* rw = Osp + (size_t)r * (2 * Kseg) + c0;
                    *(__half2*)(rw)        = hp;
                    *(__half2*)(rw + Kseg) = lp;
                } else if (mode == 2) {
                    int zz = (r / Lrow) * NH + (c0 >> 6);
                    int rr = r % Lrow, cc = c0 & 63;
                    __half2 hp, lp;
                    split2h(vx, hp.x, lp.x); split2h(vy, hp.y, lp.y);
                    __half* rw = Osp + ((size_t)zz * Lrow + rr) * (2 * DH) + cc;
                    *(__half2*)(rw)      = hp;
                    *(__half2*)(rw + DH) = lp;
                } else if (mode == 4) {
                    int zz = (r / Lrow) * NH + (c0 >> 6);
                    int rr = r % Lrow, cc = c0 & 63;
                    __half2 hp; hp.x = __float2half(vx); hp.y = __float2half(vy);
                    *(__half2*)(Osp + ((size_t)zz * Lrow + rr) * DH + cc) = hp;
                } else { // mode 3
                    int b = z >> 4, h = z & 15;
                    float* dst = (c0 < 64) ? C : C2;
                    float2 p = {vx, vy};
                    *(float2*)(dst + ((size_t)(b * LQ + r)) * HID + h * DH + (c0 & 63)) = p;
                }
            }
        }
    }
}

// ---------------- positional encoding add ------------------------------------
__global__ void add_pe_kernel(const float* __restrict__ in, float* __restrict__ out,
                              int L, size_t total)
{
    size_t idx = (size_t)blockIdx.x * blockDim.x + threadIdx.x;
    if (idx >= total) return;
    int c = (int)(idx % QD);
    int l = (int)((idx / QD) % L);
    const float coef = -9.210340371976184f / 768.0f;   // -ln(10000)/dim
    float ang = (float)l * expf((float)(c & ~1) * coef);
    float pe  = (c & 1) ? cosf(ang) : sinf(ang);
    out[idx] = in[idx] + pe;
}

// ---------------- fused softmax + att_out -------------------------------------
__global__ void __launch_bounds__(512)
softmax_attout(const float* __restrict__ scores, __half* __restrict__ atts,
               float* __restrict__ attout)
{
    extern __shared__ float sh[];   // 16 * 1024 floats
    int bx = blockIdx.x;
    int b = bx >> 9, q = bx & 511;
    int tid = threadIdx.x, w = tid >> 5, lane = tid & 31;

    const float* row = scores + ((size_t)(b * NH + w) * LQ + q) * LK;
    float4 v4[8];
    float mx = -INFINITY;
#pragma unroll
    for (int j = 0; j < 8; j++) {
        int i4 = lane + j * 32;
        v4[j] = *(const float4*)(row + i4 * 4);
        *(float4*)(sh + w * 1024 + i4 * 4) = v4[j];
        mx = fmaxf(mx, fmaxf(fmaxf(v4[j].x, v4[j].y), fmaxf(v4[j].z, v4[j].w)));
    }
#pragma unroll
    for (int o = 16; o > 0; o >>= 1) mx = fmaxf(mx, __shfl_xor_sync(0xFFFFFFFFu, mx, o));
    float sum = 0.f;
#pragma unroll
    for (int j = 0; j < 8; j++) {
        v4[j].x = expf(v4[j].x - mx); v4[j].y = expf(v4[j].y - mx);
        v4[j].z = expf(v4[j].z - mx); v4[j].w = expf(v4[j].w - mx);
        sum += (v4[j].x + v4[j].y) + (v4[j].z + v4[j].w);
    }
#pragma unroll
    for (int o = 16; o > 0; o >>= 1) sum += __shfl_xor_sync(0xFFFFFFFFu, sum, o);
    float inv = 1.f / sum;

    __half* arow = atts + ((size_t)(b * NH + w) * LQ + q) * (2 * LK);
#pragma unroll
    for (int j = 0; j < 8; j++) {
        int c = (lane + j * 32) * 4;
        float p0 = v4[j].x * inv, p1 = v4[j].y * inv;
        float p2 = v4[j].z * inv, p3 = v4[j].w * inv;
        __half2 h01, l01, h23, l23;
        split2h(p0, h01.x, l01.x); split2h(p1, h01.y, l01.y);
        split2h(p2, h23.x, l23.x); split2h(p3, h23.y, l23.y);
        *(__half2*)(arow + c)          = h01;
        *(__half2*)(arow + c + 2)      = h23;
        *(__half2*)(arow + LK + c)     = l01;
        *(__half2*)(arow + LK + c + 2) = l23;
    }
    __syncthreads();

    float s1 = 0.f, s2 = 0.f;
#pragma unroll
    for (int h = 0; h < NH; h++) {
        s1 += fmaxf(sh[h * 1024 + tid], 0.f);
        s2 += fmaxf(sh[h * 1024 + tid + 512], 0.f);
    }
    float* orow = attout + ((size_t)b * LQ + q) * LK;
    orow[tid]       = s1 * (1.f / NH);
    orow[tid + 512] = s2 * (1.f / NH);
}

// ---------------- bilinear reduce --------------------------------------------
__global__ void bilinear_kernel(const float* __restrict__ q0p,
                                const float* __restrict__ tmp,
                                float* __restrict__ xraw)
{
    int c = blockIdx.x * blockDim.x + threadIdx.x;
    int b = blockIdx.y;
    const float* a = q0p + (size_t)b * LQ * HID + c;
    const float* t = tmp + (size_t)b * LQ * HID + c;
    float s = 0.f;
    for (int v = 0; v < LQ; v++)
        s += a[(size_t)v * HID] * t[(size_t)v * HID];
    xraw[b * HID + c] = s;
}

// ---------------- custom LayerNorm (optional fused 2-term fp16 output) --------
__global__ void __launch_bounds__(256)
ln_kernel(const float* __restrict__ in1, const float* __restrict__ in2,
          const float* __restrict__ ga, const float* __restrict__ gb,
          float* __restrict__ out, __half* __restrict__ osp)
{
    size_t row = blockIdx.x;
    int t = threadIdx.x;
    const float* p1 = in1 + row * (size_t)HID;
    const float* p2 = in2 ? in2 + row * (size_t)HID : nullptr;
    float v[4];
    float s = 0.f;
#pragma unroll
    for (int i = 0; i < 4; i++) {
        int c = t + i * 256;
        v[i] = p1[c] + (p2 ? p2[c] : 0.f);
        s += v[i];
    }
    __shared__ float red[256];
    red[t] = s; __syncthreads();
    for (int o = 128; o > 0; o >>= 1) { if (t < o) red[t] += red[t + o]; __syncthreads(); }
    float mean = red[0] * (1.f / (float)HID);
    __syncthreads();
    float s2 = 0.f;
#pragma unroll
    for (int i = 0; i < 4; i++) { float d = v[i] - mean; s2 += d * d; }
    red[t] = s2; __syncthreads();
    for (int o = 128; o > 0; o >>= 1) { if (t < o) red[t] += red[t + o]; __syncthreads(); }
    float var = red[0] * (1.f / (float)(HID - 1));
    float inv = 1.f / (sqrtf(var) + 1e-6f);
#pragma unroll
    for (int i = 0; i < 4; i++) {
        int c = t + i * 256;
        float r = ga[c] * (v[i] - mean) * inv + gb[c];
        out[row * (size_t)HID + c] = r;
        if (osp) {
            __half hi, lo; split2h(r, hi, lo);
            __half* rw = osp + row * (size_t)(2 * HID);
            rw[c] = hi; rw[HID + c] = lo;
        }
    }
}

// =============================================================================
extern "C" void kernel_launch(void* const* d_in, const int* in_sizes, int n_in,
                              void* d_out, int out_size)
{
    const float* q    = (const float*)d_in[0];
    const float* k    = (const float*)d_in[1];
    const float* Wq   = (const float*)d_in[2];
    const float* bq   = (const float*)d_in[3];
    const float* Wk   = (const float*)d_in[4];
    const float* bk   = (const float*)d_in[5];
    const float* Wv   = (const float*)d_in[6];
    const float* bv   = (const float*)d_in[7];
    const float* Wv0  = (const float*)d_in[8];
    const float* bv0  = (const float*)d_in[9];
    const float* Wq0  = (const float*)d_in[10];
    const float* bq0  = (const float*)d_in[11];
    const float* nq_a = (const float*)d_in[12];
    const float* nq_b = (const float*)d_in[13];
    const float* nx_a = (const float*)d_in[14];
    const float* nx_b = (const float*)d_in[15];
    const float* W1   = (const float*)d_in[16];
    const float* b1   = (const float*)d_in[17];
    const float* W2   = (const float*)d_in[18];
    const float* b2   = (const float*)d_in[19];
    const float* ns_a = (const float*)d_in[20];
    const float* ns_b = (const float*)d_in[21];

    float* out = (float*)d_out;
    const size_t OFF_X   = 0;
    const size_t OFF_QQ  = OFF_X  + (size_t)BB * HID;
    const size_t OFF_KP  = OFF_QQ + (size_t)BB * LQ * HID;
    const size_t OFF_ATT = OFF_KP + (size_t)BB * LK * QD;

    float *qp, *q0p, *v1, *v0, *scores, *atted, *tmp, *attln, *ff, *xraw;
    __half *qpbf, *qbf, *kpbf, *attlnbf, *h1bf, *qhs, *khs, *vt, *atts;
    __half *Wqbf, *Wq0bf, *Wkbf, *Wvbf, *Wv0bf, *W1bf, *W2bf;
    cudaGetSymbolAddress((void**)&qp,     g_qp);
    cudaGetSymbolAddress((void**)&q0p,    g_q0p);
    cudaGetSymbolAddress((void**)&v1,     g_v1);
    cudaGetSymbolAddress((void**)&v0,     g_v0);
    cudaGetSymbolAddress((void**)&scores, g_scores);
    cudaGetSymbolAddress((void**)&atted,  g_atted);
    cudaGetSymbolAddress((void**)&tmp,    g_tmp);
    cudaGetSymbolAddress((void**)&attln,  g_attln);
    cudaGetSymbolAddress((void**)&ff,     g_ff);
    cudaGetSymbolAddress((void**)&xraw,   g_xraw);
    cudaGetSymbolAddress((void**)&qpbf,   g_qpbf);
    cudaGetSymbolAddress((void**)&qbf,    g_qbf);
    cudaGetSymbolAddress((void**)&kpbf,   g_kpbf);
    cudaGetSymbolAddress((void**)&attlnbf,g_attlnbf);
    cudaGetSymbolAddress((void**)&h1bf,   g_h1bf);
    cudaGetSymbolAddress((void**)&qhs,    g_qhs);
    cudaGetSymbolAddress((void**)&khs,    g_khs);
    cudaGetSymbolAddress((void**)&vt,     g_vt);
    cudaGetSymbolAddress((void**)&atts,   g_atts);
    cudaGetSymbolAddress((void**)&Wqbf,   g_Wqbf);
    cudaGetSymbolAddress((void**)&Wq0bf,  g_Wq0bf);
    cudaGetSymbolAddress((void**)&Wkbf,   g_Wkbf);
    cudaGetSymbolAddress((void**)&Wvbf,   g_Wvbf);
    cudaGetSymbolAddress((void**)&Wv0bf,  g_Wv0bf);
    cudaGetSymbolAddress((void**)&W1bf,   g_W1bf);
    cudaGetSymbolAddress((void**)&W2bf,   g_W2bf);

    cudaFuncSetAttribute(gemm_mma, cudaFuncAttributeMaxDynamicSharedMemorySize,
                         GEMM_SMEM_BYTES);
    cudaFuncSetAttribute(softmax_attout, cudaFuncAttributeMaxDynamicSharedMemorySize,
                         16 * 1024 * (int)sizeof(float));

    float* kp = out + OFF_KP;
    const int MQ = BB * LQ;     // 4096
    const int MK = BB * LK;     // 8192

    // 1) positional encodings
    {
        size_t tq = (size_t)BB * LQ * QD;
        add_pe_kernel<<<(unsigned)((tq + 255) / 256), 256>>>(q, qp, LQ, tq);
        size_t tk = (size_t)BB * LK * QD;
        add_pe_kernel<<<(unsigned)((tk + 255) / 256), 256>>>(k, kp, LK, tk);
    }

    // 2) conversions: A-side 2-term, B-side single fp16
    {
        size_t t1 = (size_t)MQ * QD;
        convA_half<<<(unsigned)((t1 + 255) / 256), 256>>>(qp, qpbf, QD, t1);
        convA_half<<<(unsigned)((t1 + 255) / 256), 256>>>(q,  qbf,  QD, t1);
        size_t t2 = (size_t)MK * QD;
        convA_half<<<(unsigned)((t2 + 255) / 256), 256>>>(kp, kpbf, QD, t2);
        dim3 bb(32, 8);
        convB_half<<<dim3(QD / 32, HID / 32), bb>>>(Wq,  Wqbf,  QD, HID);
        convB_half<<<dim3(QD / 32, HID / 32), bb>>>(Wq0, Wq0bf, QD, HID);
        convB_half<<<dim3(QD / 32, HID / 32), bb>>>(Wk,  Wkbf,  QD, HID);
        convB_half<<<dim3(QD / 32, HID / 32), bb>>>(Wv,  Wvbf,  QD, HID);
        convB_half<<<dim3(QD / 32, HID / 32), bb>>>(Wv0, Wv0bf, QD, HID);
        convB_half<<<dim3(HID / 32, MID / 32), bb>>>(W1, W1bf, HID, MID);
        convB_half<<<dim3(MID / 32, HID / 32), bb>>>(W2, W2bf, MID, HID);
    }

    // 3) projections
    gemm_mma<<<dim3(HID / 128, MQ / 128, 1), 256, GEMM_SMEM_BYTES>>>(
        qpbf, Wqbf, bq, nullptr, nullptr, qhs,
        QD, 0, 0, 0, 0, 2, 0, 0.125f, 0, LQ);          // qh -> 2-term, /8 folded
    gemm_mma<<<dim3(HID / 128, MK / 128, 1), 256, GEMM_SMEM_BYTES>>>(
        kpbf, Wkbf, bk, nullptr, nullptr, khs,
        QD, 0, 0, 0, 0, 4, 0, 1.f, 0, LK);             // kh -> single
    gemm_mma<<<dim3(HID / 128, MQ / 128, 1), 256, GEMM_SMEM_BYTES>>>(
        qbf, Wq0bf, bq0, q0p, nullptr, nullptr,
        QD, HID, 0, 0, 0, 0, 0, 1.f, 0, 0);
    gemm_mma<<<dim3(HID / 128, MK / 128, 1), 256, GEMM_SMEM_BYTES>>>(
        kpbf, Wvbf, bv, v1, nullptr, nullptr,
        QD, HID, 0, 0, 0, 0, 0, 1.f, 0, 0);
    gemm_mma<<<dim3(HID / 128, MK / 128, 1), 256, GEMM_SMEM_BYTES>>>(
        kpbf, Wv0bf, bv0, v0, nullptr, nullptr,
        QD, HID, 0, 0, 0, 0, 0, 1.f, 0, 0);

    // 4) Vt transpose (single fp16)
    vt_transpose<<<dim3(LK / 32, 128 / 32, BB * NH), dim3(32, 8)>>>(v1, v0, vt);

    // 5) scores = qhs @ khs^T (batched, K=64)
    gemm_mma<<<dim3(LK / 128, LQ / 128, BB * NH), 256, GEMM_SMEM_BYTES>>>(
        qhs, khs, nullptr, scores, nullptr, nullptr,
        DH, LK,
        (long long)LQ * 2 * DH, (long long)LK * DH, (long long)LQ * LK,
        0, 0, 1.f, 0, 0);

    // 6) fused softmax (2-term fp16 out) + att_out
    softmax_attout<<<BB * LQ, 512, 16 * 1024 * sizeof(float)>>>(
        scores, atts, out + OFF_ATT);

    // 7) [atted | tmp] = att @ [v1 | v0] (batched, N=128, K=1024)
    gemm_mma<<<dim3(1, LQ / 128, BB * NH), 256, GEMM_SMEM_BYTES>>>(
        atts, vt, nullptr, atted, tmp, nullptr,
        LK, 0,
        (long long)LQ * 2 * LK, (long long)128 * LK, 0,
        3, 0, 1.f, 0, 0);

    // 8) bilinear + LN -> x
    bilinear_kernel<<<dim3(HID / 256, BB), 256>>>(q0p, tmp, xraw);
    ln_kernel<<<BB, 256>>>(xraw, nullptr, nx_a, nx_b, out + OFF_X, nullptr);

    // 9) atted = LN(q0p + atted_raw), fused 2-term fp16 output
    ln_kernel<<<MQ, 256>>>(q0p, atted, nq_a, nq_b, attln, attlnbf);

    // 10) FFN
    gemm_mma<<<dim3(MID / 128, MQ / 128, 1), 256, GEMM_SMEM_BYTES>>>(
        attlnbf, W1bf, b1, nullptr, nullptr, h1bf,
        HID, 0, 0, 0, 0, 1, 1, 1.f, MID, 0);
    gemm_mma<<<dim3(HID / 128, MQ / 128, 1), 256, GEMM_SMEM_BYTES>>>(
        h1bf, W2bf, b2, ff, nullptr, nullptr,
        MID, HID, 0, 0, 0, 0, 0, 1.f, 0, 0);
    ln_kernel<<<MQ, 256>>>(attln, ff, ns_a, ns_b, out + OFF_QQ, nullptr);
}

// round 12
// speedup vs baseline: 2.4557x; 1.0711x over previous
#include <cuda_runtime.h>
#include <cuda_fp16.h>
#include <math.h>
#include <stdint.h>

// Problem constants
#define BB  8
#define LQ  512
#define LK  1024
#define QD  768
#define HID 1024
#define MID 4096
#define NH  16
#define DH  64

// ---------------- scratch (device globals) ------------------------------------
__device__ float  g_q0p   [(size_t)BB*LQ*HID];
__device__ float  g_v1    [(size_t)BB*LK*HID];
__device__ float  g_v0    [(size_t)BB*LK*HID];
__device__ __half g_scoresh[(size_t)BB*NH*LQ*LK];  // 134 MB fp16 pre-softmax
__device__ float  g_atted [(size_t)BB*LQ*HID];
__device__ float  g_tmp   [(size_t)BB*LQ*HID];
__device__ float  g_attln [(size_t)BB*LQ*HID];
__device__ float  g_ff    [(size_t)BB*LQ*HID];
__device__ float  g_xraw  [(size_t)BB*HID];

// fp16 operands: A-side 2-term [hi|lo] (row stride 2K), B-side single fp16.
__device__ __half g_qpbf   [(size_t)BB*LQ*2*QD];
__device__ __half g_qbf    [(size_t)BB*LQ*2*QD];
__device__ __half g_kpbf   [(size_t)BB*LK*2*QD];
__device__ __half g_attlnbf[(size_t)BB*LQ*2*HID];
__device__ __half g_h1bf   [(size_t)BB*LQ*2*MID];
__device__ __half g_qhs    [(size_t)BB*NH*LQ*2*DH];   // per-head 2-term, x0.125
__device__ __half g_khs    [(size_t)BB*NH*LK*DH];     // per-head single
__device__ __half g_vt     [(size_t)BB*NH*128*LK];    // [z][n:v1|v0] single
__device__ __half g_atts   [(size_t)BB*NH*LQ*LK];     // single-fp16 softmax probs
__device__ __half g_Wqbf  [(size_t)HID*QD];
__device__ __half g_Wq0bf [(size_t)HID*QD];
__device__ __half g_Wkbf  [(size_t)HID*QD];
__device__ __half g_Wvbf  [(size_t)HID*QD];
__device__ __half g_Wv0bf [(size_t)HID*QD];
__device__ __half g_W1bf  [(size_t)MID*HID];
__device__ __half g_W2bf  [(size_t)HID*MID];

// =================== helpers ==================================================
__device__ __forceinline__ uint32_t smem_u32(const void* p) {
    uint32_t a;
    asm("{ .reg .u64 t; cvta.to.shared.u64 t, %1; cvt.u32.u64 %0, t; }"
        : "=r"(a) : "l"(p));
    return a;
}
#define SWZ128(x) ((x) ^ (((x) >> 3) & 0x70))

__device__ __forceinline__ void cp_async16(uint32_t dst, const void* src) {
    asm volatile("cp.async.cg.shared.global [%0], [%1], 16;"
                 :: "r"(dst), "l"(src) : "memory");
}
#define CP_COMMIT() asm volatile("cp.async.commit_group;" ::: "memory")
#define CP_WAIT(n)  asm volatile("cp.async.wait_group %0;" :: "n"(n) : "memory")

__device__ __forceinline__ void ldsm_x4(uint32_t& r0, uint32_t& r1,
                                        uint32_t& r2, uint32_t& r3, uint32_t a) {
    asm volatile("ldmatrix.sync.aligned.m8n8.x4.shared.b16 {%0,%1,%2,%3}, [%4];"
                 : "=r"(r0), "=r"(r1), "=r"(r2), "=r"(r3) : "r"(a));
}
__device__ __forceinline__ void mma16816(float* c, const uint32_t* a,
                                         uint32_t b0, uint32_t b1) {
    asm volatile("mma.sync.aligned.m16n8k16.row.col.f32.f16.f16.f32 "
                 "{%0,%1,%2,%3}, {%4,%5,%6,%7}, {%8,%9}, {%0,%1,%2,%3};"
                 : "+f"(c[0]), "+f"(c[1]), "+f"(c[2]), "+f"(c[3])
                 : "r"(a[0]), "r"(a[1]), "r"(a[2]), "r"(a[3]), "r"(b0), "r"(b1));
}
__device__ __forceinline__ void split2h(float v, __half& hi, __half& lo) {
    hi = __float2half(v);
    lo = __float2half(v - __half2float(hi));
}

// ---------------- conversions --------------------------------------------------
// Fused: out = in + PE, optional fp32 store, fp16 2-term [hi | lo] store.
__global__ void add_pe_split(const float* __restrict__ in, float* __restrict__ f32out,
                             __half* __restrict__ hout, int L, size_t total)
{
    size_t idx = (size_t)blockIdx.x * blockDim.x + threadIdx.x;
    if (idx >= total) return;
    int c = (int)(idx % QD);
    int l = (int)((idx / QD) % L);
    const float coef = -9.210340371976184f / 768.0f;   // -ln(10000)/dim
    float ang = (float)l * expf((float)(c & ~1) * coef);
    float pe  = (c & 1) ? cosf(ang) : sinf(ang);
    float x = in[idx] + pe;
    if (f32out) f32out[idx] = x;
    __half hi, lo; split2h(x, hi, lo);
    __half* row = hout + (idx / QD) * (size_t)(2 * QD);
    row[c] = hi; row[QD + c] = lo;
}

// A fp32 [M,K] -> fp16 2-term [M, 2K] ([hi | lo])
__global__ void convA_half(const float* __restrict__ in, __half* __restrict__ out,
                           int K, size_t total)
{
    size_t idx = (size_t)blockIdx.x * blockDim.x + threadIdx.x;
    if (idx >= total) return;
    size_t m = idx / K;
    int    k = (int)(idx % K);
    __half hi, lo; split2h(in[idx], hi, lo);
    __half* row = out + m * (size_t)(2 * K);
    row[k] = hi; row[K + k] = lo;
}

// W [K,N] fp32 -> [N,K] fp16 single (transposed)
__global__ void convB_half(const float* __restrict__ W, __half* __restrict__ out,
                           int K, int N)
{
    __shared__ float t[32][33];
    int k0 = blockIdx.x * 32, n0 = blockIdx.y * 32;
    int x = threadIdx.x, y = threadIdx.y;   // 32 x 8
#pragma unroll
    for (int i = 0; i < 32; i += 8)
        t[y + i][x] = W[(size_t)(k0 + y + i) * N + n0 + x];
    __syncthreads();
#pragma unroll
    for (int i = 0; i < 32; i += 8) {
        int n = n0 + y + i, k = k0 + x;
        out[(size_t)n * K + k] = __float2half(t[x][y + i]);
    }
}

// v1,v0 [B*LK, HID] fp32 -> Vt [z][n(0..127: v1|v0)][LK] fp16 single
__global__ void vt_transpose(const float* __restrict__ v1, const float* __restrict__ v0,
                             __half* __restrict__ vt)
{
    __shared__ float t[32][33];
    int z = blockIdx.z, b = z >> 4, h = z & 15;
    int kk0 = blockIdx.x * 32, nd0 = blockIdx.y * 32;
    int x = threadIdx.x, y = threadIdx.y;   // 32 x 8
    const float* src = (nd0 < 64) ? v1 : v0;
    int d0 = nd0 & 63;
#pragma unroll
    for (int i = 0; i < 32; i += 8)
        t[y + i][x] = src[(size_t)(b * LK + kk0 + y + i) * HID + h * DH + d0 + x];
    __syncthreads();
#pragma unroll
    for (int i = 0; i < 32; i += 8) {
        int n = nd0 + y + i, kk = kk0 + x;
        vt[((size_t)z * 128 + n) * LK + kk] = __float2half(t[x][y + i]);
    }
}

// ---------------- fp16 mma.sync GEMM --------------------------------------------
// C[M,N] (128x128 CTA tile, 8 warps of 32x64) = asegs segment-products:
//   seg s: A(seg s) x B.   A row stride asegs*K, B row stride K.
// 3-stage cp.async pipeline, 2 CTAs/SM.
// modes: 0 = fp32 C (+z*offC); 1 = 2-term fp16 to Osp (rows 2*Kseg), bias/relu;
//        2 = per-head 2-term ((b,h), Lrow rows); 3 = att@V fp32 scatter;
//        4 = per-head single fp16; 5 = fp16 single to Osp (+z*offC, ldc).
#define STAGE_BYTES 32768               // A 16KB + B 16KB
#define GEMM_SMEM_BYTES (3 * STAGE_BYTES)

__global__ void __launch_bounds__(256, 2)
gemm_mma(const __half* __restrict__ A, const __half* __restrict__ B,
         const float* __restrict__ bias, float* __restrict__ C, float* __restrict__ C2,
         __half* __restrict__ Osp,
         int K, int ldc,
         long long offA, long long offB, long long offC,
         int mode, int relu, float scale, int Kseg, int Lrow, int asegs)
{
    extern __shared__ uint8_t dynsmem[];
    const uint32_t sb = smem_u32(dynsmem);
    const int tid = threadIdx.x;
    const int wid = tid >> 5, lane = tid & 31;
    const int m0 = blockIdx.y * 128, n0 = blockIdx.x * 128;
    const int wm = (wid & 3) * 32, wn = (wid >> 2) * 64;
    const int z = blockIdx.z;

    A += (size_t)z * offA;
    B += (size_t)z * offB;

    const int KA = asegs * K;        // A row stride
    const int cps = K >> 6;          // 64-wide chunks per segment
    const int nch = asegs * cps;
    const size_t abase = (size_t)m0 * KA;
    const size_t bbase = (size_t)n0 * K;

    float acc[2][8][4] = {};

    auto load_stage = [&](int st, int ch) {
        int seg = ch / cps;
        int w64 = (ch - seg * cps) * 64;
        int koffA = seg * K + w64;
        int koffB = w64;
        uint32_t base = (uint32_t)st * STAGE_BYTES;
#pragma unroll
        for (int i = 0; i < 4; i++) {
            int idx = tid + i * 256;
            int r = idx >> 3, c = idx & 7;
            uint32_t so = SWZ128((uint32_t)(r * 128 + c * 16));
            cp_async16(sb + base + so, A + abase + (size_t)r * KA + koffA + c * 8);
            cp_async16(sb + base + 16384u + so, B + bbase + (size_t)r * K + koffB + c * 8);
        }
        CP_COMMIT();
    };

    load_stage(0, 0);
    if (nch > 1) load_stage(1, 1);

    for (int ch = 0; ch < nch; ch++) {
        if (ch + 2 < nch) load_stage((ch + 2) % 3, ch + 2);
        if (ch + 2 < nch)      { CP_WAIT(2); }
        else if (ch + 1 < nch) { CP_WAIT(1); }
        else                   { CP_WAIT(0); }
        __syncthreads();

        uint32_t As = sb + (uint32_t)(ch % 3) * STAGE_BYTES;
        uint32_t Bs = As + 16384u;
#pragma unroll
        for (int ks = 0; ks < 4; ks++) {
            int kb = ks * 32 + ((lane >> 4) << 4);
            uint32_t a[2][4];
#pragma unroll
            for (int mi = 0; mi < 2; mi++) {
                int r = wm + mi * 16 + (lane & 15);
                ldsm_x4(a[mi][0], a[mi][1], a[mi][2], a[mi][3],
                        As + SWZ128((uint32_t)(r * 128 + kb)));
            }
            uint32_t b[4][4];
#pragma unroll
            for (int g = 0; g < 4; g++) {
                int r = wn + g * 16 + (lane & 15);
                ldsm_x4(b[g][0], b[g][1], b[g][2], b[g][3],
                        Bs + SWZ128((uint32_t)(r * 128 + kb)));
            }
#pragma unroll
            for (int mi = 0; mi < 2; mi++)
#pragma unroll
                for (int nj = 0; nj < 8; nj++) {
                    int g = nj >> 1;
                    uint32_t b0 = (nj & 1) ? b[g][1] : b[g][0];
                    uint32_t b1 = (nj & 1) ? b[g][3] : b[g][2];
                    mma16816(acc[mi][nj], a[mi], b0, b1);
                }
        }
        __syncthreads();
    }

    // ---- epilogue ----
    int rowg = lane >> 2, colg = (lane & 3) * 2;
#pragma unroll
    for (int mi = 0; mi < 2; mi++) {
#pragma unroll
        for (int nj = 0; nj < 8; nj++) {
            int c0 = n0 + wn + nj * 8 + colg;
            float bx = 0.f, by = 0.f;
            if (bias) { bx = bias[c0]; by = bias[c0 + 1]; }
#pragma unroll
            for (int half = 0; half < 2; half++) {
                int r = m0 + wm + mi * 16 + rowg + half * 8;
                float vx = (acc[mi][nj][half * 2 + 0] + bx) * scale;
                float vy = (acc[mi][nj][half * 2 + 1] + by) * scale;
                if (relu) { vx = fmaxf(vx, 0.f); vy = fmaxf(vy, 0.f); }
                if (mode == 0) {
                    float2 p = {vx, vy};
                    *(float2*)(C + (size_t)z * offC + (size_t)r * ldc + c0) = p;
                } else if (mode == 1) {
                    __half2 hp, lp;
                    split2h(vx, hp.x, lp.x); split2h(vy, hp.y, lp.y);
                    __half* rw = Osp + (size_t)r * (2 * Kseg) + c0;
                    *(__half2*)(rw)        = hp;
                    *(__half2*)(rw + Kseg) = lp;
                } else if (mode == 2) {
                    int zz = (r / Lrow) * NH + (c0 >> 6);
                    int rr = r % Lrow, cc = c0 & 63;
                    __half2 hp, lp;
                    split2h(vx, hp.x, lp.x); split2h(vy, hp.y, lp.y);
                    __half* rw = Osp + ((size_t)zz * Lrow + rr) * (2 * DH) + cc;
                    *(__half2*)(rw)      = hp;
                    *(__half2*)(rw + DH) = lp;
                } else if (mode == 4) {
                    int zz = (r / Lrow) * NH + (c0 >> 6);
                    int rr = r % Lrow, cc = c0 & 63;
                    __half2 hp; hp.x = __float2half(vx); hp.y = __float2half(vy);
                    *(__half2*)(Osp + ((size_t)zz * Lrow + rr) * DH + cc) = hp;
                } else if (mode == 5) {
                    __half2 hp; hp.x = __float2half(vx); hp.y = __float2half(vy);
                    *(__half2*)(Osp + (size_t)z * offC + (size_t)r * ldc + c0) = hp;
                } else { // mode 3
                    int b = z >> 4, h = z & 15;
                    float* dst = (c0 < 64) ? C : C2;
                    float2 p = {vx, vy};
                    *(float2*)(dst + ((size_t)(b * LQ + r)) * HID + h * DH + (c0 & 63)) = p;
                }
            }
        }
    }
}

// ---------------- fused softmax + att_out (fp16 scores in, fp16 probs out) ----
__global__ void __launch_bounds__(512)
softmax_attout(const __half* __restrict__ scores, __half* __restrict__ atts,
               float* __restrict__ attout)
{
    extern __shared__ float sh[];   // 16 * 1024 floats
    int bx = blockIdx.x;
    int b = bx >> 9, q = bx & 511;
    int tid = threadIdx.x, w = tid >> 5, lane = tid & 31;

    const __half* row = scores + ((size_t)(b * NH + w) * LQ + q) * LK;
    float v[32];
    float mx = -INFINITY;
#pragma unroll
    for (int j = 0; j < 4; j++) {
        uint4 u = ((const uint4*)row)[lane + j * 32];     // 8 halves
        const __half2* hp = (const __half2*)&u;
#pragma unroll
        for (int t2 = 0; t2 < 4; t2++) {
            float2 f = __half22float2(hp[t2]);
            int c = j * 8 + t2 * 2;
            v[c] = f.x; v[c + 1] = f.y;
            mx = fmaxf(mx, fmaxf(f.x, f.y));
        }
        // stage raw fp32 for att_out
        int cbase = (lane + j * 32) * 8;
#pragma unroll
        for (int t2 = 0; t2 < 4; t2++) {
            float2 f = __half22float2(hp[t2]);
            sh[w * 1024 + cbase + t2 * 2]     = f.x;
            sh[w * 1024 + cbase + t2 * 2 + 1] = f.y;
        }
    }
#pragma unroll
    for (int o = 16; o > 0; o >>= 1) mx = fmaxf(mx, __shfl_xor_sync(0xFFFFFFFFu, mx, o));
    float sum = 0.f;
#pragma unroll
    for (int c = 0; c < 32; c++) { v[c] = expf(v[c] - mx); sum += v[c]; }
#pragma unroll
    for (int o = 16; o > 0; o >>= 1) sum += __shfl_xor_sync(0xFFFFFFFFu, sum, o);
    float inv = 1.f / sum;

    __half* arow = atts + ((size_t)(b * NH + w) * LQ + q) * LK;
#pragma unroll
    for (int j = 0; j < 4; j++) {
        uint4 u;
        __half2* hp = (__half2*)&u;
#pragma unroll
        for (int t2 = 0; t2 < 4; t2++) {
            int c = j * 8 + t2 * 2;
            __half2 p; p.x = __float2half(v[c] * inv); p.y = __float2half(v[c + 1] * inv);
            hp[t2] = p;
        }
        ((uint4*)arow)[lane + j * 32] = u;
    }
    __syncthreads();

    float s1 = 0.f, s2 = 0.f;
#pragma unroll
    for (int h = 0; h < NH; h++) {
        s1 += fmaxf(sh[h * 1024 + tid], 0.f);
        s2 += fmaxf(sh[h * 1024 + tid + 512], 0.f);
    }
    float* orow = attout + ((size_t)b * LQ + q) * LK;
    orow[tid]       = s1 * (1.f / NH);
    orow[tid + 512] = s2 * (1.f / NH);
}

// ---------------- bilinear reduce --------------------------------------------
__global__ void bilinear_kernel(const float* __restrict__ q0p,
                                const float* __restrict__ tmp,
                                float* __restrict__ xraw)
{
    int c = blockIdx.x * blockDim.x + threadIdx.x;
    int b = blockIdx.y;
    const float* a = q0p + (size_t)b * LQ * HID + c;
    const float* t = tmp + (size_t)b * LQ * HID + c;
    float s = 0.f;
    for (int v = 0; v < LQ; v++)
        s += a[(size_t)v * HID] * t[(size_t)v * HID];
    xraw[b * HID + c] = s;
}

// ---------------- custom LayerNorm (optional fused 2-term fp16 output) --------
__global__ void __launch_bounds__(256)
ln_kernel(const float* __restrict__ in1, const float* __restrict__ in2,
          const float* __restrict__ ga, const float* __restrict__ gb,
          float* __restrict__ out, __half* __restrict__ osp)
{
    size_t row = blockIdx.x;
    int t = threadIdx.x;
    const float* p1 = in1 + row * (size_t)HID;
    const float* p2 = in2 ? in2 + row * (size_t)HID : nullptr;
    float v[4];
    float s = 0.f;
#pragma unroll
    for (int i = 0; i < 4; i++) {
        int c = t + i * 256;
        v[i] = p1[c] + (p2 ? p2[c] : 0.f);
        s += v[i];
    }
    __shared__ float red[256];
    red[t] = s; __syncthreads();
    for (int o = 128; o > 0; o >>= 1) { if (t < o) red[t] += red[t + o]; __syncthreads(); }
    float mean = red[0] * (1.f / (float)HID);
    __syncthreads();
    float s2 = 0.f;
#pragma unroll
    for (int i = 0; i < 4; i++) { float d = v[i] - mean; s2 += d * d; }
    red[t] = s2; __syncthreads();
    for (int o = 128; o > 0; o >>= 1) { if (t < o) red[t] += red[t + o]; __syncthreads(); }
    float var = red[0] * (1.f / (float)(HID - 1));
    float inv = 1.f / (sqrtf(var) + 1e-6f);
#pragma unroll
    for (int i = 0; i < 4; i++) {
        int c = t + i * 256;
        float r = ga[c] * (v[i] - mean) * inv + gb[c];
        out[row * (size_t)HID + c] = r;
        if (osp) {
            __half hi, lo; split2h(r, hi, lo);
            __half* rw = osp + row * (size_t)(2 * HID);
            rw[c] = hi; rw[HID + c] = lo;
        }
    }
}

// =============================================================================
extern "C" void kernel_launch(void* const* d_in, const int* in_sizes, int n_in,
                              void* d_out, int out_size)
{
    const float* q    = (const float*)d_in[0];
    const float* k    = (const float*)d_in[1];
    const float* Wq   = (const float*)d_in[2];
    const float* bq   = (const float*)d_in[3];
    const float* Wk   = (const float*)d_in[4];
    const float* bk   = (const float*)d_in[5];
    const float* Wv   = (const float*)d_in[6];
    const float* bv   = (const float*)d_in[7];
    const float* Wv0  = (const float*)d_in[8];
    const float* bv0  = (const float*)d_in[9];
    const float* Wq0  = (const float*)d_in[10];
    const float* bq0  = (const float*)d_in[11];
    const float* nq_a = (const float*)d_in[12];
    const float* nq_b = (const float*)d_in[13];
    const float* nx_a = (const float*)d_in[14];
    const float* nx_b = (const float*)d_in[15];
    const float* W1   = (const float*)d_in[16];
    const float* b1   = (const float*)d_in[17];
    const float* W2   = (const float*)d_in[18];
    const float* b2   = (const float*)d_in[19];
    const float* ns_a = (const float*)d_in[20];
    const float* ns_b = (const float*)d_in[21];

    float* out = (float*)d_out;
    const size_t OFF_X   = 0;
    const size_t OFF_QQ  = OFF_X  + (size_t)BB * HID;
    const size_t OFF_KP  = OFF_QQ + (size_t)BB * LQ * HID;
    const size_t OFF_ATT = OFF_KP + (size_t)BB * LK * QD;

    float *q0p, *v1, *v0, *atted, *tmp, *attln, *ff, *xraw;
    __half *scoresh, *qpbf, *qbf, *kpbf, *attlnbf, *h1bf, *qhs, *khs, *vt, *atts;
    __half *Wqbf, *Wq0bf, *Wkbf, *Wvbf, *Wv0bf, *W1bf, *W2bf;
    cudaGetSymbolAddress((void**)&q0p,    g_q0p);
    cudaGetSymbolAddress((void**)&v1,     g_v1);
    cudaGetSymbolAddress((void**)&v0,     g_v0);
    cudaGetSymbolAddress((void**)&scoresh,g_scoresh);
    cudaGetSymbolAddress((void**)&atted,  g_atted);
    cudaGetSymbolAddress((void**)&tmp,    g_tmp);
    cudaGetSymbolAddress((void**)&attln,  g_attln);
    cudaGetSymbolAddress((void**)&ff,     g_ff);
    cudaGetSymbolAddress((void**)&xraw,   g_xraw);
    cudaGetSymbolAddress((void**)&qpbf,   g_qpbf);
    cudaGetSymbolAddress((void**)&qbf,    g_qbf);
    cudaGetSymbolAddress((void**)&kpbf,   g_kpbf);
    cudaGetSymbolAddress((void**)&attlnbf,g_attlnbf);
    cudaGetSymbolAddress((void**)&h1bf,   g_h1bf);
    cudaGetSymbolAddress((void**)&qhs,    g_qhs);
    cudaGetSymbolAddress((void**)&khs,    g_khs);
    cudaGetSymbolAddress((void**)&vt,     g_vt);
    cudaGetSymbolAddress((void**)&atts,   g_atts);
    cudaGetSymbolAddress((void**)&Wqbf,   g_Wqbf);
    cudaGetSymbolAddress((void**)&Wq0bf,  g_Wq0bf);
    cudaGetSymbolAddress((void**)&Wkbf,   g_Wkbf);
    cudaGetSymbolAddress((void**)&Wvbf,   g_Wvbf);
    cudaGetSymbolAddress((void**)&Wv0bf,  g_Wv0bf);
    cudaGetSymbolAddress((void**)&W1bf,   g_W1bf);
    cudaGetSymbolAddress((void**)&W2bf,   g_W2bf);

    cudaFuncSetAttribute(gemm_mma, cudaFuncAttributeMaxDynamicSharedMemorySize,
                         GEMM_SMEM_BYTES);
    cudaFuncSetAttribute(softmax_attout, cudaFuncAttributeMaxDynamicSharedMemorySize,
                         16 * 1024 * (int)sizeof(float));

    float* kp = out + OFF_KP;
    const int MQ = BB * LQ;     // 4096
    const int MK = BB * LK;     // 8192

    // 1) positional encodings fused with fp16 2-term split
    {
        size_t tq = (size_t)MQ * QD;
        add_pe_split<<<(unsigned)((tq + 255) / 256), 256>>>(q, nullptr, qpbf, LQ, tq);
        size_t tk = (size_t)MK * QD;
        add_pe_split<<<(unsigned)((tk + 255) / 256), 256>>>(k, kp, kpbf, LK, tk);
        convA_half<<<(unsigned)((tq + 255) / 256), 256>>>(q, qbf, QD, tq);
    }

    // 2) weight conversions (single fp16, transposed)
    {
        dim3 bb(32, 8);
        convB_half<<<dim3(QD / 32, HID / 32), bb>>>(Wq,  Wqbf,  QD, HID);
        convB_half<<<dim3(QD / 32, HID / 32), bb>>>(Wq0, Wq0bf, QD, HID);
        convB_half<<<dim3(QD / 32, HID / 32), bb>>>(Wk,  Wkbf,  QD, HID);
        convB_half<<<dim3(QD / 32, HID / 32), bb>>>(Wv,  Wvbf,  QD, HID);
        convB_half<<<dim3(QD / 32, HID / 32), bb>>>(Wv0, Wv0bf, QD, HID);
        convB_half<<<dim3(HID / 32, MID / 32), bb>>>(W1, W1bf, HID, MID);
        convB_half<<<dim3(MID / 32, HID / 32), bb>>>(W2, W2bf, MID, HID);
    }

    // 3) projections (A 2-term)
    gemm_mma<<<dim3(HID / 128, MQ / 128, 1), 256, GEMM_SMEM_BYTES>>>(
        qpbf, Wqbf, bq, nullptr, nullptr, qhs,
        QD, 0, 0, 0, 0, 2, 0, 0.125f, 0, LQ, 2);       // qh -> 2-term, /8 folded
    gemm_mma<<<dim3(HID / 128, MK / 128, 1), 256, GEMM_SMEM_BYTES>>>(
        kpbf, Wkbf, bk, nullptr, nullptr, khs,
        QD, 0, 0, 0, 0, 4, 0, 1.f, 0, LK, 2);          // kh -> single
    gemm_mma<<<dim3(HID / 128, MQ / 128, 1), 256, GEMM_SMEM_BYTES>>>(
        qbf, Wq0bf, bq0, q0p, nullptr, nullptr,
        QD, HID, 0, 0, 0, 0, 0, 1.f, 0, 0, 2);
    gemm_mma<<<dim3(HID / 128, MK / 128, 1), 256, GEMM_SMEM_BYTES>>>(
        kpbf, Wvbf, bv, v1, nullptr, nullptr,
        QD, HID, 0, 0, 0, 0, 0, 1.f, 0, 0, 2);
    gemm_mma<<<dim3(HID / 128, MK / 128, 1), 256, GEMM_SMEM_BYTES>>>(
        kpbf, Wv0bf, bv0, v0, nullptr, nullptr,
        QD, HID, 0, 0, 0, 0, 0, 1.f, 0, 0, 2);

    // 4) Vt transpose (single fp16)
    vt_transpose<<<dim3(LK / 32, 128 / 32, BB * NH), dim3(32, 8)>>>(v1, v0, vt);

    // 5) scores = qhs @ khs^T -> fp16 (batched, K=64, mode 5)
    gemm_mma<<<dim3(LK / 128, LQ / 128, BB * NH), 256, GEMM_SMEM_BYTES>>>(
        qhs, khs, nullptr, nullptr, nullptr, scoresh,
        DH, LK,
        (long long)LQ * 2 * DH, (long long)LK * DH, (long long)LQ * LK,
        5, 0, 1.f, 0, 0, 2);

    // 6) fused softmax (single fp16 probs) + att_out
    softmax_attout<<<BB * LQ, 512, 16 * 1024 * sizeof(float)>>>(
        scoresh, atts, out + OFF_ATT);

    // 7) [atted | tmp] = att @ [v1 | v0] (batched, N=128, K=1024, 1 segment)
    gemm_mma<<<dim3(1, LQ / 128, BB * NH), 256, GEMM_SMEM_BYTES>>>(
        atts, vt, nullptr, atted, tmp, nullptr,
        LK, 0,
        (long long)LQ * LK, (long long)128 * LK, 0,
        3, 0, 1.f, 0, 0, 1);

    // 8) bilinear + LN -> x
    bilinear_kernel<<<dim3(HID / 256, BB), 256>>>(q0p, tmp, xraw);
    ln_kernel<<<BB, 256>>>(xraw, nullptr, nx_a, nx_b, out + OFF_X, nullptr);

    // 9) atted = LN(q0p + atted_raw), fused 2-term fp16 output
    ln_kernel<<<MQ, 256>>>(q0p, atted, nq_a, nq_b, attln, attlnbf);

    // 10) FFN
    gemm_mma<<<dim3(MID / 128, MQ / 128, 1), 256, GEMM_SMEM_BYTES>>>(
        attlnbf, W1bf, b1, nullptr, nullptr, h1bf,
        HID, 0, 0, 0, 0, 1, 1, 1.f, MID, 0, 2);
    gemm_mma<<<dim3(HID / 128, MQ / 128, 1), 256, GEMM_SMEM_BYTES>>>(
        h1bf, W2bf, b2, ff, nullptr, nullptr,
        MID, HID, 0, 0, 0, 0, 0, 1.f, 0, 0, 2);
    ln_kernel<<<MQ, 256>>>(attln, ff, ns_a, ns_b, out + OFF_QQ, nullptr);
}

// round 13
// speedup vs baseline: 2.4600x; 1.0018x over previous
#include <cuda_runtime.h>
#include <cuda_fp16.h>
#include <math.h>
#include <stdint.h>

// Problem constants
#define BB  8
#define LQ  512
#define LK  1024
#define QD  768
#define HID 1024
#define MID 4096
#define NH  16
#define DH  64

// ---------------- scratch (device globals) ------------------------------------
__device__ float  g_q0p   [(size_t)BB*LQ*HID];
__device__ float  g_v1    [(size_t)BB*LK*HID];
__device__ float  g_v0    [(size_t)BB*LK*HID];
__device__ __half g_scoresh[(size_t)BB*NH*LQ*LK];  // 134 MB fp16 pre-softmax
__device__ float  g_atted [(size_t)BB*LQ*HID];
__device__ float  g_tmp   [(size_t)BB*LQ*HID];
__device__ float  g_attln [(size_t)BB*LQ*HID];
__device__ float  g_ff    [(size_t)BB*LQ*HID];
__device__ float  g_xraw  [(size_t)BB*HID];

// fp16 operands: A-side 2-term [hi|lo] (row stride 2K), B-side single fp16.
__device__ __half g_qpbf   [(size_t)BB*LQ*2*QD];
__device__ __half g_qbf    [(size_t)BB*LQ*2*QD];
__device__ __half g_kpbf   [(size_t)BB*LK*2*QD];
__device__ __half g_attlnbf[(size_t)BB*LQ*2*HID];
__device__ __half g_h1bf   [(size_t)BB*LQ*2*MID];
__device__ __half g_qhs    [(size_t)BB*NH*LQ*2*DH];   // per-head 2-term, x0.125
__device__ __half g_khs    [(size_t)BB*NH*LK*DH];     // per-head single
__device__ __half g_vt     [(size_t)BB*NH*128*LK];    // [z][n:v1|v0] single
__device__ __half g_atts   [(size_t)BB*NH*LQ*LK];     // single-fp16 softmax probs
__device__ __half g_Wqbf  [(size_t)HID*QD];
__device__ __half g_Wq0bf [(size_t)HID*QD];
__device__ __half g_Wkbf  [(size_t)HID*QD];
__device__ __half g_Wvbf  [(size_t)HID*QD];
__device__ __half g_Wv0bf [(size_t)HID*QD];
__device__ __half g_W1bf  [(size_t)MID*HID];
__device__ __half g_W2bf  [(size_t)HID*MID];

// =================== helpers ==================================================
__device__ __forceinline__ uint32_t smem_u32(const void* p) {
    uint32_t a;
    asm("{ .reg .u64 t; cvta.to.shared.u64 t, %1; cvt.u32.u64 %0, t; }"
        : "=r"(a) : "l"(p));
    return a;
}
#define SWZ128(x) ((x) ^ (((x) >> 3) & 0x70))

__device__ __forceinline__ void cp_async16(uint32_t dst, const void* src) {
    asm volatile("cp.async.cg.shared.global [%0], [%1], 16;"
                 :: "r"(dst), "l"(src) : "memory");
}
#define CP_COMMIT() asm volatile("cp.async.commit_group;" ::: "memory")
#define CP_WAIT(n)  asm volatile("cp.async.wait_group %0;" :: "n"(n) : "memory")

__device__ __forceinline__ void ldsm_x4(uint32_t& r0, uint32_t& r1,
                                        uint32_t& r2, uint32_t& r3, uint32_t a) {
    asm volatile("ldmatrix.sync.aligned.m8n8.x4.shared.b16 {%0,%1,%2,%3}, [%4];"
                 : "=r"(r0), "=r"(r1), "=r"(r2), "=r"(r3) : "r"(a));
}
__device__ __forceinline__ void mma16816(float* c, const uint32_t* a,
                                         uint32_t b0, uint32_t b1) {
    asm volatile("mma.sync.aligned.m16n8k16.row.col.f32.f16.f16.f32 "
                 "{%0,%1,%2,%3}, {%4,%5,%6,%7}, {%8,%9}, {%0,%1,%2,%3};"
                 : "+f"(c[0]), "+f"(c[1]), "+f"(c[2]), "+f"(c[3])
                 : "r"(a[0]), "r"(a[1]), "r"(a[2]), "r"(a[3]), "r"(b0), "r"(b1));
}
__device__ __forceinline__ void split2h(float v, __half& hi, __half& lo) {
    hi = __float2half(v);
    lo = __float2half(v - __half2float(hi));
}

// ---------------- conversions --------------------------------------------------
// Fused: out = in + PE, optional fp32 store, fp16 2-term [hi | lo] store.
__global__ void add_pe_split(const float* __restrict__ in, float* __restrict__ f32out,
                             __half* __restrict__ hout, int L, size_t total)
{
    size_t idx = (size_t)blockIdx.x * blockDim.x + threadIdx.x;
    if (idx >= total) return;
    int c = (int)(idx % QD);
    int l = (int)((idx / QD) % L);
    const float coef = -9.210340371976184f / 768.0f;   // -ln(10000)/dim
    float ang = (float)l * expf((float)(c & ~1) * coef);
    float pe  = (c & 1) ? cosf(ang) : sinf(ang);
    float x = in[idx] + pe;
    if (f32out) f32out[idx] = x;
    __half hi, lo; split2h(x, hi, lo);
    __half* row = hout + (idx / QD) * (size_t)(2 * QD);
    row[c] = hi; row[QD + c] = lo;
}

// A fp32 [M,K] -> fp16 2-term [M, 2K] ([hi | lo])
__global__ void convA_half(const float* __restrict__ in, __half* __restrict__ out,
                           int K, size_t total)
{
    size_t idx = (size_t)blockIdx.x * blockDim.x + threadIdx.x;
    if (idx >= total) return;
    size_t m = idx / K;
    int    k = (int)(idx % K);
    __half hi, lo; split2h(in[idx], hi, lo);
    __half* row = out + m * (size_t)(2 * K);
    row[k] = hi; row[K + k] = lo;
}

// W [K,N] fp32 -> [N,K] fp16 single (transposed)
__global__ void convB_half(const float* __restrict__ W, __half* __restrict__ out,
                           int K, int N)
{
    __shared__ float t[32][33];
    int k0 = blockIdx.x * 32, n0 = blockIdx.y * 32;
    int x = threadIdx.x, y = threadIdx.y;   // 32 x 8
#pragma unroll
    for (int i = 0; i < 32; i += 8)
        t[y + i][x] = W[(size_t)(k0 + y + i) * N + n0 + x];
    __syncthreads();
#pragma unroll
    for (int i = 0; i < 32; i += 8) {
        int n = n0 + y + i, k = k0 + x;
        out[(size_t)n * K + k] = __float2half(t[x][y + i]);
    }
}

// v1,v0 [B*LK, HID] fp32 -> Vt [z][n(0..127: v1|v0)][LK] fp16 single
__global__ void vt_transpose(const float* __restrict__ v1, const float* __restrict__ v0,
                             __half* __restrict__ vt)
{
    __shared__ float t[32][33];
    int z = blockIdx.z, b = z >> 4, h = z & 15;
    int kk0 = blockIdx.x * 32, nd0 = blockIdx.y * 32;
    int x = threadIdx.x, y = threadIdx.y;   // 32 x 8
    const float* src = (nd0 < 64) ? v1 : v0;
    int d0 = nd0 & 63;
#pragma unroll
    for (int i = 0; i < 32; i += 8)
        t[y + i][x] = src[(size_t)(b * LK + kk0 + y + i) * HID + h * DH + d0 + x];
    __syncthreads();
#pragma unroll
    for (int i = 0; i < 32; i += 8) {
        int n = nd0 + y + i, kk = kk0 + x;
        vt[((size_t)z * 128 + n) * LK + kk] = __float2half(t[x][y + i]);
    }
}

// ---------------- fp16 mma.sync GEMM --------------------------------------------
// C[M,N] (128x128 CTA tile, 8 warps of 32x64) = asegs segment-products:
//   seg s: A(seg s) x B.   A row stride asegs*K, B row stride K.
// 3-stage cp.async pipeline, 2 CTAs/SM.
// modes: 0 = fp32 C (+z*offC); 1 = 2-term fp16 to Osp (rows 2*Kseg), bias/relu;
//        2 = per-head 2-term ((b,h), Lrow rows); 3 = att@V fp32 scatter;
//        4 = per-head single fp16; 5 = fp16 single to Osp (+z*offC, ldc).
#define STAGE_BYTES 32768               // A 16KB + B 16KB
#define GEMM_SMEM_BYTES (3 * STAGE_BYTES)

__global__ void __launch_bounds__(256, 2)
gemm_mma(const __half* __restrict__ A, const __half* __restrict__ B,
         const float* __restrict__ bias, float* __restrict__ C, float* __restrict__ C2,
         __half* __restrict__ Osp,
         int K, int ldc,
         long long offA, long long offB, long long offC,
         int mode, int relu, float scale, int Kseg, int Lrow, int asegs)
{
    extern __shared__ uint8_t dynsmem[];
    const uint32_t sb = smem_u32(dynsmem);
    const int tid = threadIdx.x;
    const int wid = tid >> 5, lane = tid & 31;
    const int m0 = blockIdx.y * 128, n0 = blockIdx.x * 128;
    const int wm = (wid & 3) * 32, wn = (wid >> 2) * 64;
    const int z = blockIdx.z;

    A += (size_t)z * offA;
    B += (size_t)z * offB;

    const int KA = asegs * K;        // A row stride
    const int cps = K >> 6;          // 64-wide chunks per segment
    const int nch = asegs * cps;
    const size_t abase = (size_t)m0 * KA;
    const size_t bbase = (size_t)n0 * K;

    float acc[2][8][4] = {};

    auto load_stage = [&](int st, int ch) {
        int seg = ch / cps;
        int w64 = (ch - seg * cps) * 64;
        int koffA = seg * K + w64;
        int koffB = w64;
        uint32_t base = (uint32_t)st * STAGE_BYTES;
#pragma unroll
        for (int i = 0; i < 4; i++) {
            int idx = tid + i * 256;
            int r = idx >> 3, c = idx & 7;
            uint32_t so = SWZ128((uint32_t)(r * 128 + c * 16));
            cp_async16(sb + base + so, A + abase + (size_t)r * KA + koffA + c * 8);
            cp_async16(sb + base + 16384u + so, B + bbase + (size_t)r * K + koffB + c * 8);
        }
        CP_COMMIT();
    };

    load_stage(0, 0);
    if (nch > 1) load_stage(1, 1);

    for (int ch = 0; ch < nch; ch++) {
        if (ch + 2 < nch) load_stage((ch + 2) % 3, ch + 2);
        if (ch + 2 < nch)      { CP_WAIT(2); }
        else if (ch + 1 < nch) { CP_WAIT(1); }
        else                   { CP_WAIT(0); }
        __syncthreads();

        uint32_t As = sb + (uint32_t)(ch % 3) * STAGE_BYTES;
        uint32_t Bs = As + 16384u;
#pragma unroll
        for (int ks = 0; ks < 4; ks++) {
            int kb = ks * 32 + ((lane >> 4) << 4);
            uint32_t a[2][4];
#pragma unroll
            for (int mi = 0; mi < 2; mi++) {
                int r = wm + mi * 16 + (lane & 15);
                ldsm_x4(a[mi][0], a[mi][1], a[mi][2], a[mi][3],
                        As + SWZ128((uint32_t)(r * 128 + kb)));
            }
            uint32_t b[4][4];
#pragma unroll
            for (int g = 0; g < 4; g++) {
                int r = wn + g * 16 + (lane & 15);
                ldsm_x4(b[g][0], b[g][1], b[g][2], b[g][3],
                        Bs + SWZ128((uint32_t)(r * 128 + kb)));
            }
#pragma unroll
            for (int mi = 0; mi < 2; mi++)
#pragma unroll
                for (int nj = 0; nj < 8; nj++) {
                    int g = nj >> 1;
                    uint32_t b0 = (nj & 1) ? b[g][1] : b[g][0];
                    uint32_t b1 = (nj & 1) ? b[g][3] : b[g][2];
                    mma16816(acc[mi][nj], a[mi], b0, b1);
                }
        }
        __syncthreads();
    }

    // ---- epilogue ----
    int rowg = lane >> 2, colg = (lane & 3) * 2;
#pragma unroll
    for (int mi = 0; mi < 2; mi++) {
#pragma unroll
        for (int nj = 0; nj < 8; nj++) {
            int c0 = n0 + wn + nj * 8 + colg;
            float bx = 0.f, by = 0.f;
            if (bias) { bx = bias[c0]; by = bias[c0 + 1]; }
#pragma unroll
            for (int half = 0; half < 2; half++) {
                int r = m0 + wm + mi * 16 + rowg + half * 8;
                float vx = (acc[mi][nj][half * 2 + 0] + bx) * scale;
                float vy = (acc[mi][nj][half * 2 + 1] + by) * scale;
                if (relu) { vx = fmaxf(vx, 0.f); vy = fmaxf(vy, 0.f); }
                if (mode == 0) {
                    float2 p = {vx, vy};
                    *(float2*)(C + (size_t)z * offC + (size_t)r * ldc + c0) = p;
                } else if (mode == 1) {
                    __half2 hp, lp;
                    split2h(vx, hp.x, lp.x); split2h(vy, hp.y, lp.y);
                    __half* rw = Osp + (size_t)r * (2 * Kseg) + c0;
                    *(__half2*)(rw)        = hp;
                    *(__half2*)(rw + Kseg) = lp;
                } else if (mode == 2) {
                    int zz = (r / Lrow) * NH + (c0 >> 6);
                    int rr = r % Lrow, cc = c0 & 63;
                    __half2 hp, lp;
                    split2h(vx, hp.x, lp.x); split2h(vy, hp.y, lp.y);
                    __half* rw = Osp + ((size_t)zz * Lrow + rr) * (2 * DH) + cc;
                    *(__half2*)(rw)      = hp;
                    *(__half2*)(rw + DH) = lp;
                } else if (mode == 4) {
                    int zz = (r / Lrow) * NH + (c0 >> 6);
                    int rr = r % Lrow, cc = c0 & 63;
                    __half2 hp; hp.x = __float2half(vx); hp.y = __float2half(vy);
                    *(__half2*)(Osp + ((size_t)zz * Lrow + rr) * DH + cc) = hp;
                } else if (mode == 5) {
                    __half2 hp; hp.x = __float2half(vx); hp.y = __float2half(vy);
                    *(__half2*)(Osp + (size_t)z * offC + (size_t)r * ldc + c0) = hp;
                } else { // mode 3
                    int b = z >> 4, h = z & 15;
                    float* dst = (c0 < 64) ? C : C2;
                    float2 p = {vx, vy};
                    *(float2*)(dst + ((size_t)(b * LQ + r)) * HID + h * DH + (c0 & 63)) = p;
                }
            }
        }
    }
}

// ---------------- fused softmax + att_out (fp16 scores in, fp16 probs out) ----
__global__ void __launch_bounds__(512)
softmax_attout(const __half* __restrict__ scores, __half* __restrict__ atts,
               float* __restrict__ attout)
{
    extern __shared__ float sh[];   // 16 * 1024 floats
    int bx = blockIdx.x;
    int b = bx >> 9, q = bx & 511;
    int tid = threadIdx.x, w = tid >> 5, lane = tid & 31;

    const __half* row = scores + ((size_t)(b * NH + w) * LQ + q) * LK;
    float v[32];
    float mx = -INFINITY;
#pragma unroll
    for (int j = 0; j < 4; j++) {
        uint4 u = ((const uint4*)row)[lane + j * 32];     // 8 halves
        const __half2* hp = (const __half2*)&u;
#pragma unroll
        for (int t2 = 0; t2 < 4; t2++) {
            float2 f = __half22float2(hp[t2]);
            int c = j * 8 + t2 * 2;
            v[c] = f.x; v[c + 1] = f.y;
            mx = fmaxf(mx, fmaxf(f.x, f.y));
        }
        // stage raw fp32 for att_out
        int cbase = (lane + j * 32) * 8;
#pragma unroll
        for (int t2 = 0; t2 < 4; t2++) {
            float2 f = __half22float2(hp[t2]);
            sh[w * 1024 + cbase + t2 * 2]     = f.x;
            sh[w * 1024 + cbase + t2 * 2 + 1] = f.y;
        }
    }
#pragma unroll
    for (int o = 16; o > 0; o >>= 1) mx = fmaxf(mx, __shfl_xor_sync(0xFFFFFFFFu, mx, o));
    float sum = 0.f;
#pragma unroll
    for (int c = 0; c < 32; c++) { v[c] = expf(v[c] - mx); sum += v[c]; }
#pragma unroll
    for (int o = 16; o > 0; o >>= 1) sum += __shfl_xor_sync(0xFFFFFFFFu, sum, o);
    float inv = 1.f / sum;

    __half* arow = atts + ((size_t)(b * NH + w) * LQ + q) * LK;
#pragma unroll
    for (int j = 0; j < 4; j++) {
        uint4 u;
        __half2* hp = (__half2*)&u;
#pragma unroll
        for (int t2 = 0; t2 < 4; t2++) {
            int c = j * 8 + t2 * 2;
            __half2 p; p.x = __float2half(v[c] * inv); p.y = __float2half(v[c + 1] * inv);
            hp[t2] = p;
        }
        ((uint4*)arow)[lane + j * 32] = u;
    }
    __syncthreads();

    float s1 = 0.f, s2 = 0.f;
#pragma unroll
    for (int h = 0; h < NH; h++) {
        s1 += fmaxf(sh[h * 1024 + tid], 0.f);
        s2 += fmaxf(sh[h * 1024 + tid + 512], 0.f);
    }
    float* orow = attout + ((size_t)b * LQ + q) * LK;
    orow[tid]       = s1 * (1.f / NH);
    orow[tid + 512] = s2 * (1.f / NH);
}

// ---------------- bilinear reduce --------------------------------------------
__global__ void bilinear_kernel(const float* __restrict__ q0p,
                                const float* __restrict__ tmp,
                                float* __restrict__ xraw)
{
    int c = blockIdx.x * blockDim.x + threadIdx.x;
    int b = blockIdx.y;
    const float* a = q0p + (size_t)b * LQ * HID + c;
    const float* t = tmp + (size_t)b * LQ * HID + c;
    float s = 0.f;
    for (int v = 0; v < LQ; v++)
        s += a[(size_t)v * HID] * t[(size_t)v * HID];
    xraw[b * HID + c] = s;
}

// ---------------- custom LayerNorm (optional fused 2-term fp16 output) --------
__global__ void __launch_bounds__(256)
ln_kernel(const float* __restrict__ in1, const float* __restrict__ in2,
          const float* __restrict__ ga, const float* __restrict__ gb,
          float* __restrict__ out, __half* __restrict__ osp)
{
    size_t row = blockIdx.x;
    int t = threadIdx.x;
    const float* p1 = in1 + row * (size_t)HID;
    const float* p2 = in2 ? in2 + row * (size_t)HID : nullptr;
    float v[4];
    float s = 0.f;
#pragma unroll
    for (int i = 0; i < 4; i++) {
        int c = t + i * 256;
        v[i] = p1[c] + (p2 ? p2[c] : 0.f);
        s += v[i];
    }
    __shared__ float red[256];
    red[t] = s; __syncthreads();
    for (int o = 128; o > 0; o >>= 1) { if (t < o) red[t] += red[t + o]; __syncthreads(); }
    float mean = red[0] * (1.f / (float)HID);
    __syncthreads();
    float s2 = 0.f;
#pragma unroll
    for (int i = 0; i < 4; i++) { float d = v[i] - mean; s2 += d * d; }
    red[t] = s2; __syncthreads();
    for (int o = 128; o > 0; o >>= 1) { if (t < o) red[t] += red[t + o]; __syncthreads(); }
    float var = red[0] * (1.f / (float)(HID - 1));
    float inv = 1.f / (sqrtf(var) + 1e-6f);
#pragma unroll
    for (int i = 0; i < 4; i++) {
        int c = t + i * 256;
        float r = ga[c] * (v[i] - mean) * inv + gb[c];
        out[row * (size_t)HID + c] = r;
        if (osp) {
            __half hi, lo; split2h(r, hi, lo);
            __half* rw = osp + row * (size_t)(2 * HID);
            rw[c] = hi; rw[HID + c] = lo;
        }
    }
}

// =============================================================================
extern "C" void kernel_launch(void* const* d_in, const int* in_sizes, int n_in,
                              void* d_out, int out_size)
{
    const float* q    = (const float*)d_in[0];
    const float* k    = (const float*)d_in[1];
    const float* Wq   = (const float*)d_in[2];
    const float* bq   = (const float*)d_in[3];
    const float* Wk   = (const float*)d_in[4];
    const float* bk   = (const float*)d_in[5];
    const float* Wv   = (const float*)d_in[6];
    const float* bv   = (const float*)d_in[7];
    const float* Wv0  = (const float*)d_in[8];
    const float* bv0  = (const float*)d_in[9];
    const float* Wq0  = (const float*)d_in[10];
    const float* bq0  = (const float*)d_in[11];
    const float* nq_a = (const float*)d_in[12];
    const float* nq_b = (const float*)d_in[13];
    const float* nx_a = (const float*)d_in[14];
    const float* nx_b = (const float*)d_in[15];
    const float* W1   = (const float*)d_in[16];
    const float* b1   = (const float*)d_in[17];
    const float* W2   = (const float*)d_in[18];
    const float* b2   = (const float*)d_in[19];
    const float* ns_a = (const float*)d_in[20];
    const float* ns_b = (const float*)d_in[21];

    float* out = (float*)d_out;
    const size_t OFF_X   = 0;
    const size_t OFF_QQ  = OFF_X  + (size_t)BB * HID;
    const size_t OFF_KP  = OFF_QQ + (size_t)BB * LQ * HID;
    const size_t OFF_ATT = OFF_KP + (size_t)BB * LK * QD;

    float *q0p, *v1, *v0, *atted, *tmp, *attln, *ff, *xraw;
    __half *scoresh, *qpbf, *qbf, *kpbf, *attlnbf, *h1bf, *qhs, *khs, *vt, *atts;
    __half *Wqbf, *Wq0bf, *Wkbf, *Wvbf, *Wv0bf, *W1bf, *W2bf;
    cudaGetSymbolAddress((void**)&q0p,    g_q0p);
    cudaGetSymbolAddress((void**)&v1,     g_v1);
    cudaGetSymbolAddress((void**)&v0,     g_v0);
    cudaGetSymbolAddress((void**)&scoresh,g_scoresh);
    cudaGetSymbolAddress((void**)&atted,  g_atted);
    cudaGetSymbolAddress((void**)&tmp,    g_tmp);
    cudaGetSymbolAddress((void**)&attln,  g_attln);
    cudaGetSymbolAddress((void**)&ff,     g_ff);
    cudaGetSymbolAddress((void**)&xraw,   g_xraw);
    cudaGetSymbolAddress((void**)&qpbf,   g_qpbf);
    cudaGetSymbolAddress((void**)&qbf,    g_qbf);
    cudaGetSymbolAddress((void**)&kpbf,   g_kpbf);
    cudaGetSymbolAddress((void**)&attlnbf,g_attlnbf);
    cudaGetSymbolAddress((void**)&h1bf,   g_h1bf);
    cudaGetSymbolAddress((void**)&qhs,    g_qhs);
    cudaGetSymbolAddress((void**)&khs,    g_khs);
    cudaGetSymbolAddress((void**)&vt,     g_vt);
    cudaGetSymbolAddress((void**)&atts,   g_atts);
    cudaGetSymbolAddress((void**)&Wqbf,   g_Wqbf);
    cudaGetSymbolAddress((void**)&Wq0bf,  g_Wq0bf);
    cudaGetSymbolAddress((void**)&Wkbf,   g_Wkbf);
    cudaGetSymbolAddress((void**)&Wvbf,   g_Wvbf);
    cudaGetSymbolAddress((void**)&Wv0bf,  g_Wv0bf);
    cudaGetSymbolAddress((void**)&W1bf,   g_W1bf);
    cudaGetSymbolAddress((void**)&W2bf,   g_W2bf);

    cudaFuncSetAttribute(gemm_mma, cudaFuncAttributeMaxDynamicSharedMemorySize,
                         GEMM_SMEM_BYTES);
    cudaFuncSetAttribute(softmax_attout, cudaFuncAttributeMaxDynamicSharedMemorySize,
                         16 * 1024 * (int)sizeof(float));

    float* kp = out + OFF_KP;
    const int MQ = BB * LQ;     // 4096
    const int MK = BB * LK;     // 8192

    // 1) positional encodings fused with fp16 2-term split
    {
        size_t tq = (size_t)MQ * QD;
        add_pe_split<<<(unsigned)((tq + 255) / 256), 256>>>(q, nullptr, qpbf, LQ, tq);
        size_t tk = (size_t)MK * QD;
        add_pe_split<<<(unsigned)((tk + 255) / 256), 256>>>(k, kp, kpbf, LK, tk);
        convA_half<<<(unsigned)((tq + 255) / 256), 256>>>(q, qbf, QD, tq);
    }

    // 2) weight conversions (single fp16, transposed)
    {
        dim3 bb(32, 8);
        convB_half<<<dim3(QD / 32, HID / 32), bb>>>(Wq,  Wqbf,  QD, HID);
        convB_half<<<dim3(QD / 32, HID / 32), bb>>>(Wq0, Wq0bf, QD, HID);
        convB_half<<<dim3(QD / 32, HID / 32), bb>>>(Wk,  Wkbf,  QD, HID);
        convB_half<<<dim3(QD / 32, HID / 32), bb>>>(Wv,  Wvbf,  QD, HID);
        convB_half<<<dim3(QD / 32, HID / 32), bb>>>(Wv0, Wv0bf, QD, HID);
        convB_half<<<dim3(HID / 32, MID / 32), bb>>>(W1, W1bf, HID, MID);
        convB_half<<<dim3(MID / 32, HID / 32), bb>>>(W2, W2bf, MID, HID);
    }

    // 3) projections (A 2-term)
    gemm_mma<<<dim3(HID / 128, MQ / 128, 1), 256, GEMM_SMEM_BYTES>>>(
        qpbf, Wqbf, bq, nullptr, nullptr, qhs,
        QD, 0, 0, 0, 0, 2, 0, 0.125f, 0, LQ, 2);       // qh -> 2-term, /8 folded
    gemm_mma<<<dim3(HID / 128, MK / 128, 1), 256, GEMM_SMEM_BYTES>>>(
        kpbf, Wkbf, bk, nullptr, nullptr, khs,
        QD, 0, 0, 0, 0, 4, 0, 1.f, 0, LK, 2);          // kh -> single
    gemm_mma<<<dim3(HID / 128, MQ / 128, 1), 256, GEMM_SMEM_BYTES>>>(
        qbf, Wq0bf, bq0, q0p, nullptr, nullptr,
        QD, HID, 0, 0, 0, 0, 0, 1.f, 0, 0, 2);
    gemm_mma<<<dim3(HID / 128, MK / 128, 1), 256, GEMM_SMEM_BYTES>>>(
        kpbf, Wvbf, bv, v1, nullptr, nullptr,
        QD, HID, 0, 0, 0, 0, 0, 1.f, 0, 0, 2);
    gemm_mma<<<dim3(HID / 128, MK / 128, 1), 256, GEMM_SMEM_BYTES>>>(
        kpbf, Wv0bf, bv0, v0, nullptr, nullptr,
        QD, HID, 0, 0, 0, 0, 0, 1.f, 0, 0, 2);

    // 4) Vt transpose (single fp16)
    vt_transpose<<<dim3(LK / 32, 128 / 32, BB * NH), dim3(32, 8)>>>(v1, v0, vt);

    // 5) scores = qhs @ khs^T -> fp16 (batched, K=64, mode 5)
    gemm_mma<<<dim3(LK / 128, LQ / 128, BB * NH), 256, GEMM_SMEM_BYTES>>>(
        qhs, khs, nullptr, nullptr, nullptr, scoresh,
        DH, LK,
        (long long)LQ * 2 * DH, (long long)LK * DH, (long long)LQ * LK,
        5, 0, 1.f, 0, 0, 2);

    // 6) fused softmax (single fp16 probs) + att_out
    softmax_attout<<<BB * LQ, 512, 16 * 1024 * sizeof(float)>>>(
        scoresh, atts, out + OFF_ATT);

    // 7) [atted | tmp] = att @ [v1 | v0] (batched, N=128, K=1024, 1 segment)
    gemm_mma<<<dim3(1, LQ / 128, BB * NH), 256, GEMM_SMEM_BYTES>>>(
        atts, vt, nullptr, atted, tmp, nullptr,
        LK, 0,
        (long long)LQ * LK, (long long)128 * LK, 0,
        3, 0, 1.f, 0, 0, 1);

    // 8) bilinear + LN -> x
    bilinear_kernel<<<dim3(HID / 256, BB), 256>>>(q0p, tmp, xraw);
    ln_kernel<<<BB, 256>>>(xraw, nullptr, nx_a, nx_b, out + OFF_X, nullptr);

    // 9) atted = LN(q0p + atted_raw), fused 2-term fp16 output
    ln_kernel<<<MQ, 256>>>(q0p, atted, nq_a, nq_b, attln, attlnbf);

    // 10) FFN
    gemm_mma<<<dim3(MID / 128, MQ / 128, 1), 256, GEMM_SMEM_BYTES>>>(
        attlnbf, W1bf, b1, nullptr, nullptr, h1bf,
        HID, 0, 0, 0, 0, 1, 1, 1.f, MID, 0, 2);
    gemm_mma<<<dim3(HID / 128, MQ / 128, 1), 256, GEMM_SMEM_BYTES>>>(
        h1bf, W2bf, b2, ff, nullptr, nullptr,
        MID, HID, 0, 0, 0, 0, 0, 1.f, 0, 0, 2);
    ln_kernel<<<MQ, 256>>>(attln, ff, ns_a, ns_b, out + OFF_QQ, nullptr);
}

// round 15
// speedup vs baseline: 2.4612x; 1.0005x over previous
#include <cuda_runtime.h>
#include <cuda_fp16.h>
#include <math.h>
#include <stdint.h>

// Problem constants
#define BB  8
#define LQ  512
#define LK  1024
#define QD  768
#define HID 1024
#define MID 4096
#define NH  16
#define DH  64

// ---------------- scratch (device globals) ------------------------------------
__device__ float  g_q0p   [(size_t)BB*LQ*HID];
__device__ float  g_v1    [(size_t)BB*LK*HID];
__device__ float  g_v0    [(size_t)BB*LK*HID];
__device__ __half g_scoresh[(size_t)BB*NH*LQ*LK];  // 134 MB fp16 pre-softmax
__device__ float  g_atted [(size_t)BB*LQ*HID];
__device__ float  g_tmp   [(size_t)BB*LQ*HID];
__device__ float  g_attln [(size_t)BB*LQ*HID];
__device__ float  g_ff    [(size_t)BB*LQ*HID];
__device__ float  g_xraw  [(size_t)BB*HID];

// fp16 operands: A-side 2-term [hi|lo] (row stride 2K), B-side single fp16.
__device__ __half g_qpbf   [(size_t)BB*LQ*2*QD];
__device__ __half g_qbf    [(size_t)BB*LQ*2*QD];
__device__ __half g_kpbf   [(size_t)BB*LK*2*QD];
__device__ __half g_attlnbf[(size_t)BB*LQ*2*HID];
__device__ __half g_h1bf   [(size_t)BB*LQ*2*MID];
__device__ __half g_qhs    [(size_t)BB*NH*LQ*2*DH];   // per-head 2-term, x0.125
__device__ __half g_khs    [(size_t)BB*NH*LK*DH];     // per-head single
__device__ __half g_vt     [(size_t)BB*NH*128*LK];    // [z][n:v1|v0] single
__device__ __half g_atts   [(size_t)BB*NH*LQ*LK];     // single-fp16 softmax probs
__device__ __half g_Wqbf  [(size_t)HID*QD];
__device__ __half g_Wq0bf [(size_t)HID*QD];
__device__ __half g_Wkbf  [(size_t)HID*QD];
__device__ __half g_Wvbf  [(size_t)HID*QD];
__device__ __half g_Wv0bf [(size_t)HID*QD];
__device__ __half g_W1bf  [(size_t)MID*HID];
__device__ __half g_W2bf  [(size_t)HID*MID];

// =================== helpers ==================================================
__device__ __forceinline__ uint32_t smem_u32(const void* p) {
    uint32_t a;
    asm("{ .reg .u64 t; cvta.to.shared.u64 t, %1; cvt.u32.u64 %0, t; }"
        : "=r"(a) : "l"(p));
    return a;
}
#define SWZ128(x) ((x) ^ (((x) >> 3) & 0x70))

__device__ __forceinline__ void cp_async16(uint32_t dst, const void* src) {
    asm volatile("cp.async.cg.shared.global [%0], [%1], 16;"
                 :: "r"(dst), "l"(src) : "memory");
}
#define CP_COMMIT() asm volatile("cp.async.commit_group;" ::: "memory")
#define CP_WAIT(n)  asm volatile("cp.async.wait_group %0;" :: "n"(n) : "memory")

__device__ __forceinline__ void ldsm_x4(uint32_t& r0, uint32_t& r1,
                                        uint32_t& r2, uint32_t& r3, uint32_t a) {
    asm volatile("ldmatrix.sync.aligned.m8n8.x4.shared.b16 {%0,%1,%2,%3}, [%4];"
                 : "=r"(r0), "=r"(r1), "=r"(r2), "=r"(r3) : "r"(a));
}
__device__ __forceinline__ void mma16816(float* c, const uint32_t* a,
                                         uint32_t b0, uint32_t b1) {
    asm volatile("mma.sync.aligned.m16n8k16.row.col.f32.f16.f16.f32 "
                 "{%0,%1,%2,%3}, {%4,%5,%6,%7}, {%8,%9}, {%0,%1,%2,%3};"
                 : "+f"(c[0]), "+f"(c[1]), "+f"(c[2]), "+f"(c[3])
                 : "r"(a[0]), "r"(a[1]), "r"(a[2]), "r"(a[3]), "r"(b0), "r"(b1));
}
__device__ __forceinline__ void split2h(float v, __half& hi, __half& lo) {
    hi = __float2half(v);
    lo = __float2half(v - __half2float(hi));
}

// ---------------- conversions --------------------------------------------------
// Fused: out = in + PE, optional fp32 store, fp16 2-term [hi | lo] store.
__global__ void add_pe_split(const float* __restrict__ in, float* __restrict__ f32out,
                             __half* __restrict__ hout, int L, size_t total)
{
    size_t idx = (size_t)blockIdx.x * blockDim.x + threadIdx.x;
    if (idx >= total) return;
    int c = (int)(idx % QD);
    int l = (int)((idx / QD) % L);
    const float coef = -9.210340371976184f / 768.0f;   // -ln(10000)/dim
    float ang = (float)l * expf((float)(c & ~1) * coef);
    float pe  = (c & 1) ? cosf(ang) : sinf(ang);
    float x = in[idx] + pe;
    if (f32out) f32out[idx] = x;
    __half hi, lo; split2h(x, hi, lo);
    __half* row = hout + (idx / QD) * (size_t)(2 * QD);
    row[c] = hi; row[QD + c] = lo;
}

// A fp32 [M,K] -> fp16 2-term [M, 2K] ([hi | lo])
__global__ void convA_half(const float* __restrict__ in, __half* __restrict__ out,
                           int K, size_t total)
{
    size_t idx = (size_t)blockIdx.x * blockDim.x + threadIdx.x;
    if (idx >= total) return;
    size_t m = idx / K;
    int    k = (int)(idx % K);
    __half hi, lo; split2h(in[idx], hi, lo);
    __half* row = out + m * (size_t)(2 * K);
    row[k] = hi; row[K + k] = lo;
}

// W [K,N] fp32 -> [N,K] fp16 single (transposed)
__global__ void convB_half(const float* __restrict__ W, __half* __restrict__ out,
                           int K, int N)
{
    __shared__ float t[32][33];
    int k0 = blockIdx.x * 32, n0 = blockIdx.y * 32;
    int x = threadIdx.x, y = threadIdx.y;   // 32 x 8
#pragma unroll
    for (int i = 0; i < 32; i += 8)
        t[y + i][x] = W[(size_t)(k0 + y + i) * N + n0 + x];
    __syncthreads();
#pragma unroll
    for (int i = 0; i < 32; i += 8) {
        int n = n0 + y + i, k = k0 + x;
        out[(size_t)n * K + k] = __float2half(t[x][y + i]);
    }
}

// v1,v0 [B*LK, HID] fp32 -> Vt [z][n(0..127: v1|v0)][LK] fp16 single
__global__ void vt_transpose(const float* __restrict__ v1, const float* __restrict__ v0,
                             __half* __restrict__ vt)
{
    __shared__ float t[32][33];
    int z = blockIdx.z, b = z >> 4, h = z & 15;
    int kk0 = blockIdx.x * 32, nd0 = blockIdx.y * 32;
    int x = threadIdx.x, y = threadIdx.y;   // 32 x 8
    const float* src = (nd0 < 64) ? v1 : v0;
    int d0 = nd0 & 63;
#pragma unroll
    for (int i = 0; i < 32; i += 8)
        t[y + i][x] = src[(size_t)(b * LK + kk0 + y + i) * HID + h * DH + d0 + x];
    __syncthreads();
#pragma unroll
    for (int i = 0; i < 32; i += 8) {
        int n = nd0 + y + i, kk = kk0 + x;
        vt[((size_t)z * 128 + n) * LK + kk] = __float2half(t[x][y + i]);
    }
}

// ---------------- fp16 mma.sync GEMM --------------------------------------------
// C[M,N] (128x128 CTA tile, 8 warps of 32x64) = asegs segment-products:
//   seg s: A(seg s) x B.   A row stride asegs*K, B row stride K.
// 3-stage cp.async pipeline, 2 CTAs/SM.
// modes: 0 = fp32 C (+z*offC); 1 = 2-term fp16 to Osp (rows 2*Kseg), bias/relu;
//        2 = per-head 2-term ((b,h), Lrow rows); 3 = att@V fp32 scatter;
//        4 = per-head single fp16; 5 = fp16 single to Osp (+z*offC, ldc).
#define STAGE_BYTES 32768               // A 16KB + B 16KB
#define GEMM_SMEM_BYTES (3 * STAGE_BYTES)

__global__ void __launch_bounds__(256, 2)
gemm_mma(const __half* __restrict__ A, const __half* __restrict__ B,
         const float* __restrict__ bias, float* __restrict__ C, float* __restrict__ C2,
         __half* __restrict__ Osp,
         int K, int ldc,
         long long offA, long long offB, long long offC,
         int mode, int relu, float scale, int Kseg, int Lrow, int asegs)
{
    extern __shared__ uint8_t dynsmem[];
    const uint32_t sb = smem_u32(dynsmem);
    const int tid = threadIdx.x;
    const int wid = tid >> 5, lane = tid & 31;
    const int m0 = blockIdx.y * 128, n0 = blockIdx.x * 128;
    const int wm = (wid & 3) * 32, wn = (wid >> 2) * 64;
    const int z = blockIdx.z;

    A += (size_t)z * offA;
    B += (size_t)z * offB;

    const int KA = asegs * K;        // A row stride
    const int cps = K >> 6;          // 64-wide chunks per segment
    const int nch = asegs * cps;
    const size_t abase = (size_t)m0 * KA;
    const size_t bbase = (size_t)n0 * K;

    float acc[2][8][4] = {};

    auto load_stage = [&](int st, int ch) {
        int seg = ch / cps;
        int w64 = (ch - seg * cps) * 64;
        int koffA = seg * K + w64;
        int koffB = w64;
        uint32_t base = (uint32_t)st * STAGE_BYTES;
#pragma unroll
        for (int i = 0; i < 4; i++) {
            int idx = tid + i * 256;
            int r = idx >> 3, c = idx & 7;
            uint32_t so = SWZ128((uint32_t)(r * 128 + c * 16));
            cp_async16(sb + base + so, A + abase + (size_t)r * KA + koffA + c * 8);
            cp_async16(sb + base + 16384u + so, B + bbase + (size_t)r * K + koffB + c * 8);
        }
        CP_COMMIT();
    };

    load_stage(0, 0);
    if (nch > 1) load_stage(1, 1);

    for (int ch = 0; ch < nch; ch++) {
        if (ch + 2 < nch) load_stage((ch + 2) % 3, ch + 2);
        if (ch + 2 < nch)      { CP_WAIT(2); }
        else if (ch + 1 < nch) { CP_WAIT(1); }
        else                   { CP_WAIT(0); }
        __syncthreads();

        uint32_t As = sb + (uint32_t)(ch % 3) * STAGE_BYTES;
        uint32_t Bs = As + 16384u;
#pragma unroll
        for (int ks = 0; ks < 4; ks++) {
            int kb = ks * 32 + ((lane >> 4) << 4);
            uint32_t a[2][4];
#pragma unroll
            for (int mi = 0; mi < 2; mi++) {
                int r = wm + mi * 16 + (lane & 15);
                ldsm_x4(a[mi][0], a[mi][1], a[mi][2], a[mi][3],
                        As + SWZ128((uint32_t)(r * 128 + kb)));
            }
            uint32_t b[4][4];
#pragma unroll
            for (int g = 0; g < 4; g++) {
                int r = wn + g * 16 + (lane & 15);
                ldsm_x4(b[g][0], b[g][1], b[g][2], b[g][3],
                        Bs + SWZ128((uint32_t)(r * 128 + kb)));
            }
#pragma unroll
            for (int mi = 0; mi < 2; mi++)
#pragma unroll
                for (int nj = 0; nj < 8; nj++) {
                    int g = nj >> 1;
                    uint32_t b0 = (nj & 1) ? b[g][1] : b[g][0];
                    uint32_t b1 = (nj & 1) ? b[g][3] : b[g][2];
                    mma16816(acc[mi][nj], a[mi], b0, b1);
                }
        }
        __syncthreads();
    }

    // ---- epilogue ----
    int rowg = lane >> 2, colg = (lane & 3) * 2;
#pragma unroll
    for (int mi = 0; mi < 2; mi++) {
#pragma unroll
        for (int nj = 0; nj < 8; nj++) {
            int c0 = n0 + wn + nj * 8 + colg;
            float bx = 0.f, by = 0.f;
            if (bias) { bx = bias[c0]; by = bias[c0 + 1]; }
#pragma unroll
            for (int half = 0; half < 2; half++) {
                int r = m0 + wm + mi * 16 + rowg + half * 8;
                float vx = (acc[mi][nj][half * 2 + 0] + bx) * scale;
                float vy = (acc[mi][nj][half * 2 + 1] + by) * scale;
                if (relu) { vx = fmaxf(vx, 0.f); vy = fmaxf(vy, 0.f); }
                if (mode == 0) {
                    float2 p = {vx, vy};
                    *(float2*)(C + (size_t)z * offC + (size_t)r * ldc + c0) = p;
                } else if (mode == 1) {
                    __half2 hp, lp;
                    split2h(vx, hp.x, lp.x); split2h(vy, hp.y, lp.y);
                    __half* rw = Osp + (size_t)r * (2 * Kseg) + c0;
                    *(__half2*)(rw)        = hp;
                    *(__half2*)(rw + Kseg) = lp;
                } else if (mode == 2) {
                    int zz = (r / Lrow) * NH + (c0 >> 6);
                    int rr = r % Lrow, cc = c0 & 63;
                    __half2 hp, lp;
                    split2h(vx, hp.x, lp.x); split2h(vy, hp.y, lp.y);
                    __half* rw = Osp + ((size_t)zz * Lrow + rr) * (2 * DH) + cc;
                    *(__half2*)(rw)      = hp;
                    *(__half2*)(rw + DH) = lp;
                } else if (mode == 4) {
                    int zz = (r / Lrow) * NH + (c0 >> 6);
                    int rr = r % Lrow, cc = c0 & 63;
                    __half2 hp; hp.x = __float2half(vx); hp.y = __float2half(vy);
                    *(__half2*)(Osp + ((size_t)zz * Lrow + rr) * DH + cc) = hp;
                } else if (mode == 5) {
                    __half2 hp; hp.x = __float2half(vx); hp.y = __float2half(vy);
                    *(__half2*)(Osp + (size_t)z * offC + (size_t)r * ldc + c0) = hp;
                } else { // mode 3
                    int b = z >> 4, h = z & 15;
                    float* dst = (c0 < 64) ? C : C2;
                    float2 p = {vx, vy};
                    *(float2*)(dst + ((size_t)(b * LQ + r)) * HID + h * DH + (c0 & 63)) = p;
                }
            }
        }
    }
}

// ---------------- fused softmax + att_out (fp16 scores in, fp16 probs out) ----
__global__ void __launch_bounds__(512)
softmax_attout(const __half* __restrict__ scores, __half* __restrict__ atts,
               float* __restrict__ attout)
{
    extern __shared__ float sh[];   // 16 * 1024 floats
    int bx = blockIdx.x;
    int b = bx >> 9, q = bx & 511;
    int tid = threadIdx.x, w = tid >> 5, lane = tid & 31;

    const __half* row = scores + ((size_t)(b * NH + w) * LQ + q) * LK;
    float v[32];
    float mx = -INFINITY;
#pragma unroll
    for (int j = 0; j < 4; j++) {
        uint4 u = ((const uint4*)row)[lane + j * 32];     // 8 halves
        const __half2* hp = (const __half2*)&u;
#pragma unroll
        for (int t2 = 0; t2 < 4; t2++) {
            float2 f = __half22float2(hp[t2]);
            int c = j * 8 + t2 * 2;
            v[c] = f.x; v[c + 1] = f.y;
            mx = fmaxf(mx, fmaxf(f.x, f.y));
        }
        // stage raw fp32 for att_out
        int cbase = (lane + j * 32) * 8;
#pragma unroll
        for (int t2 = 0; t2 < 4; t2++) {
            float2 f = __half22float2(hp[t2]);
            sh[w * 1024 + cbase + t2 * 2]     = f.x;
            sh[w * 1024 + cbase + t2 * 2 + 1] = f.y;
        }
    }
#pragma unroll
    for (int o = 16; o > 0; o >>= 1) mx = fmaxf(mx, __shfl_xor_sync(0xFFFFFFFFu, mx, o));
    float sum = 0.f;
#pragma unroll
    for (int c = 0; c < 32; c++) { v[c] = expf(v[c] - mx); sum += v[c]; }
#pragma unroll
    for (int o = 16; o > 0; o >>= 1) sum += __shfl_xor_sync(0xFFFFFFFFu, sum, o);
    float inv = 1.f / sum;

    __half* arow = atts + ((size_t)(b * NH + w) * LQ + q) * LK;
#pragma unroll
    for (int j = 0; j < 4; j++) {
        uint4 u;
        __half2* hp = (__half2*)&u;
#pragma unroll
        for (int t2 = 0; t2 < 4; t2++) {
            int c = j * 8 + t2 * 2;
            __half2 p; p.x = __float2half(v[c] * inv); p.y = __float2half(v[c + 1] * inv);
            hp[t2] = p;
        }
        ((uint4*)arow)[lane + j * 32] = u;
    }
    __syncthreads();

    float s1 = 0.f, s2 = 0.f;
#pragma unroll
    for (int h = 0; h < NH; h++) {
        s1 += fmaxf(sh[h * 1024 + tid], 0.f);
        s2 += fmaxf(sh[h * 1024 + tid + 512], 0.f);
    }
    float* orow = attout + ((size_t)b * LQ + q) * LK;
    orow[tid]       = s1 * (1.f / NH);
    orow[tid + 512] = s2 * (1.f / NH);
}

// ---------------- bilinear reduce --------------------------------------------
__global__ void bilinear_kernel(const float* __restrict__ q0p,
                                const float* __restrict__ tmp,
                                float* __restrict__ xraw)
{
    int c = blockIdx.x * blockDim.x + threadIdx.x;
    int b = blockIdx.y;
    const float* a = q0p + (size_t)b * LQ * HID + c;
    const float* t = tmp + (size_t)b * LQ * HID + c;
    float s = 0.f;
    for (int v = 0; v < LQ; v++)
        s += a[(size_t)v * HID] * t[(size_t)v * HID];
    xraw[b * HID + c] = s;
}

// ---------------- custom LayerNorm (optional fused 2-term fp16 output) --------
__global__ void __launch_bounds__(256)
ln_kernel(const float* __restrict__ in1, const float* __restrict__ in2,
          const float* __restrict__ ga, const float* __restrict__ gb,
          float* __restrict__ out, __half* __restrict__ osp)
{
    size_t row = blockIdx.x;
    int t = threadIdx.x;
    const float* p1 = in1 + row * (size_t)HID;
    const float* p2 = in2 ? in2 + row * (size_t)HID : nullptr;
    float v[4];
    float s = 0.f;
#pragma unroll
    for (int i = 0; i < 4; i++) {
        int c = t + i * 256;
        v[i] = p1[c] + (p2 ? p2[c] : 0.f);
        s += v[i];
    }
    __shared__ float red[256];
    red[t] = s; __syncthreads();
    for (int o = 128; o > 0; o >>= 1) { if (t < o) red[t] += red[t + o]; __syncthreads(); }
    float mean = red[0] * (1.f / (float)HID);
    __syncthreads();
    float s2 = 0.f;
#pragma unroll
    for (int i = 0; i < 4; i++) { float d = v[i] - mean; s2 += d * d; }
    red[t] = s2; __syncthreads();
    for (int o = 128; o > 0; o >>= 1) { if (t < o) red[t] += red[t + o]; __syncthreads(); }
    float var = red[0] * (1.f / (float)(HID - 1));
    float inv = 1.f / (sqrtf(var) + 1e-6f);
#pragma unroll
    for (int i = 0; i < 4; i++) {
        int c = t + i * 256;
        float r = ga[c] * (v[i] - mean) * inv + gb[c];
        out[row * (size_t)HID + c] = r;
        if (osp) {
            __half hi, lo; split2h(r, hi, lo);
            __half* rw = osp + row * (size_t)(2 * HID);
            rw[c] = hi; rw[HID + c] = lo;
        }
    }
}

// =============================================================================
extern "C" void kernel_launch(void* const* d_in, const int* in_sizes, int n_in,
                              void* d_out, int out_size)
{
    const float* q    = (const float*)d_in[0];
    const float* k    = (const float*)d_in[1];
    const float* Wq   = (const float*)d_in[2];
    const float* bq   = (const float*)d_in[3];
    const float* Wk   = (const float*)d_in[4];
    const float* bk   = (const float*)d_in[5];
    const float* Wv   = (const float*)d_in[6];
    const float* bv   = (const float*)d_in[7];
    const float* Wv0  = (const float*)d_in[8];
    const float* bv0  = (const float*)d_in[9];
    const float* Wq0  = (const float*)d_in[10];
    const float* bq0  = (const float*)d_in[11];
    const float* nq_a = (const float*)d_in[12];
    const float* nq_b = (const float*)d_in[13];
    const float* nx_a = (const float*)d_in[14];
    const float* nx_b = (const float*)d_in[15];
    const float* W1   = (const float*)d_in[16];
    const float* b1   = (const float*)d_in[17];
    const float* W2   = (const float*)d_in[18];
    const float* b2   = (const float*)d_in[19];
    const float* ns_a = (const float*)d_in[20];
    const float* ns_b = (const float*)d_in[21];

    float* out = (float*)d_out;
    const size_t OFF_X   = 0;
    const size_t OFF_QQ  = OFF_X  + (size_t)BB * HID;
    const size_t OFF_KP  = OFF_QQ + (size_t)BB * LQ * HID;
    const size_t OFF_ATT = OFF_KP + (size_t)BB * LK * QD;

    float *q0p, *v1, *v0, *atted, *tmp, *attln, *ff, *xraw;
    __half *scoresh, *qpbf, *qbf, *kpbf, *attlnbf, *h1bf, *qhs, *khs, *vt, *atts;
    __half *Wqbf, *Wq0bf, *Wkbf, *Wvbf, *Wv0bf, *W1bf, *W2bf;
    cudaGetSymbolAddress((void**)&q0p,    g_q0p);
    cudaGetSymbolAddress((void**)&v1,     g_v1);
    cudaGetSymbolAddress((void**)&v0,     g_v0);
    cudaGetSymbolAddress((void**)&scoresh,g_scoresh);
    cudaGetSymbolAddress((void**)&atted,  g_atted);
    cudaGetSymbolAddress((void**)&tmp,    g_tmp);
    cudaGetSymbolAddress((void**)&attln,  g_attln);
    cudaGetSymbolAddress((void**)&ff,     g_ff);
    cudaGetSymbolAddress((void**)&xraw,   g_xraw);
    cudaGetSymbolAddress((void**)&qpbf,   g_qpbf);
    cudaGetSymbolAddress((void**)&qbf,    g_qbf);
    cudaGetSymbolAddress((void**)&kpbf,   g_kpbf);
    cudaGetSymbolAddress((void**)&attlnbf,g_attlnbf);
    cudaGetSymbolAddress((void**)&h1bf,   g_h1bf);
    cudaGetSymbolAddress((void**)&qhs,    g_qhs);
    cudaGetSymbolAddress((void**)&khs,    g_khs);
    cudaGetSymbolAddress((void**)&vt,     g_vt);
    cudaGetSymbolAddress((void**)&atts,   g_atts);
    cudaGetSymbolAddress((void**)&Wqbf,   g_Wqbf);
    cudaGetSymbolAddress((void**)&Wq0bf,  g_Wq0bf);
    cudaGetSymbolAddress((void**)&Wkbf,   g_Wkbf);
    cudaGetSymbolAddress((void**)&Wvbf,   g_Wvbf);
    cudaGetSymbolAddress((void**)&Wv0bf,  g_Wv0bf);
    cudaGetSymbolAddress((void**)&W1bf,   g_W1bf);
    cudaGetSymbolAddress((void**)&W2bf,   g_W2bf);

    cudaFuncSetAttribute(gemm_mma, cudaFuncAttributeMaxDynamicSharedMemorySize,
                         GEMM_SMEM_BYTES);
    cudaFuncSetAttribute(softmax_attout, cudaFuncAttributeMaxDynamicSharedMemorySize,
                         16 * 1024 * (int)sizeof(float));

    float* kp = out + OFF_KP;
    const int MQ = BB * LQ;     // 4096
    const int MK = BB * LK;     // 8192

    // 1) positional encodings fused with fp16 2-term split
    {
        size_t tq = (size_t)MQ * QD;
        add_pe_split<<<(unsigned)((tq + 255) / 256), 256>>>(q, nullptr, qpbf, LQ, tq);
        size_t tk = (size_t)MK * QD;
        add_pe_split<<<(unsigned)((tk + 255) / 256), 256>>>(k, kp, kpbf, LK, tk);
        convA_half<<<(unsigned)((tq + 255) / 256), 256>>>(q, qbf, QD, tq);
    }

    // 2) weight conversions (single fp16, transposed)
    {
        dim3 bb(32, 8);
        convB_half<<<dim3(QD / 32, HID / 32), bb>>>(Wq,  Wqbf,  QD, HID);
        convB_half<<<dim3(QD / 32, HID / 32), bb>>>(Wq0, Wq0bf, QD, HID);
        convB_half<<<dim3(QD / 32, HID / 32), bb>>>(Wk,  Wkbf,  QD, HID);
        convB_half<<<dim3(QD / 32, HID / 32), bb>>>(Wv,  Wvbf,  QD, HID);
        convB_half<<<dim3(QD / 32, HID / 32), bb>>>(Wv0, Wv0bf, QD, HID);
        convB_half<<<dim3(HID / 32, MID / 32), bb>>>(W1, W1bf, HID, MID);
        convB_half<<<dim3(MID / 32, HID / 32), bb>>>(W2, W2bf, MID, HID);
    }

    // 3) projections (A 2-term)
    gemm_mma<<<dim3(HID / 128, MQ / 128, 1), 256, GEMM_SMEM_BYTES>>>(
        qpbf, Wqbf, bq, nullptr, nullptr, qhs,
        QD, 0, 0, 0, 0, 2, 0, 0.125f, 0, LQ, 2);       // qh -> 2-term, /8 folded
    gemm_mma<<<dim3(HID / 128, MK / 128, 1), 256, GEMM_SMEM_BYTES>>>(
        kpbf, Wkbf, bk, nullptr, nullptr, khs,
        QD, 0, 0, 0, 0, 4, 0, 1.f, 0, LK, 2);          // kh -> single
    gemm_mma<<<dim3(HID / 128, MQ / 128, 1), 256, GEMM_SMEM_BYTES>>>(
        qbf, Wq0bf, bq0, q0p, nullptr, nullptr,
        QD, HID, 0, 0, 0, 0, 0, 1.f, 0, 0, 2);
    gemm_mma<<<dim3(HID / 128, MK / 128, 1), 256, GEMM_SMEM_BYTES>>>(
        kpbf, Wvbf, bv, v1, nullptr, nullptr,
        QD, HID, 0, 0, 0, 0, 0, 1.f, 0, 0, 2);
    gemm_mma<<<dim3(HID / 128, MK / 128, 1), 256, GEMM_SMEM_BYTES>>>(
        kpbf, Wv0bf, bv0, v0, nullptr, nullptr,
        QD, HID, 0, 0, 0, 0, 0, 1.f, 0, 0, 2);

    // 4) Vt transpose (single fp16)
    vt_transpose<<<dim3(LK / 32, 128 / 32, BB * NH), dim3(32, 8)>>>(v1, v0, vt);

    // 5) scores = qhs @ khs^T -> fp16 (batched, K=64, mode 5)
    gemm_mma<<<dim3(LK / 128, LQ / 128, BB * NH), 256, GEMM_SMEM_BYTES>>>(
        qhs, khs, nullptr, nullptr, nullptr, scoresh,
        DH, LK,
        (long long)LQ * 2 * DH, (long long)LK * DH, (long long)LQ * LK,
        5, 0, 1.f, 0, 0, 2);

    // 6) fused softmax (single fp16 probs) + att_out
    softmax_attout<<<BB * LQ, 512, 16 * 1024 * sizeof(float)>>>(
        scoresh, atts, out + OFF_ATT);

    // 7) [atted | tmp] = att @ [v1 | v0] (batched, N=128, K=1024, 1 segment)
    gemm_mma<<<dim3(1, LQ / 128, BB * NH), 256, GEMM_SMEM_BYTES>>>(
        atts, vt, nullptr, atted, tmp, nullptr,
        LK, 0,
        (long long)LQ * LK, (long long)128 * LK, 0,
        3, 0, 1.f, 0, 0, 1);

    // 8) bilinear + LN -> x
    bilinear_kernel<<<dim3(HID / 256, BB), 256>>>(q0p, tmp, xraw);
    ln_kernel<<<BB, 256>>>(xraw, nullptr, nx_a, nx_b, out + OFF_X, nullptr);

    // 9) atted = LN(q0p + atted_raw), fused 2-term fp16 output
    ln_kernel<<<MQ, 256>>>(q0p, atted, nq_a, nq_b, attln, attlnbf);

    // 10) FFN
    gemm_mma<<<dim3(MID / 128, MQ / 128, 1), 256, GEMM_SMEM_BYTES>>>(
        attlnbf, W1bf, b1, nullptr, nullptr, h1bf,
        HID, 0, 0, 0, 0, 1, 1, 1.f, MID, 0, 2);
    gemm_mma<<<dim3(HID / 128, MQ / 128, 1), 256, GEMM_SMEM_BYTES>>>(
        h1bf, W2bf, b2, ff, nullptr, nullptr,
        MID, HID, 0, 0, 0, 0, 0, 1.f, 0, 0, 2);
    ln_kernel<<<MQ, 256>>>(attln, ff, ns_a, ns_b, out + OFF_QQ, nullptr);
}